// round 4
// baseline (speedup 1.0000x reference)
#include <cuda_runtime.h>
#include <cuda_bf16.h>
#include <math.h>
#include <cstdint>

#define BATCH 128
#define SEQ   49
#define HID   512
#define VOCAB 32000
#define NSTEP 15
#define BH    (BATCH*HID)
#define GPAD  36

// ---------------- device scratch ----------------
__device__ float g_x[BATCH*NSTEP*HID];
__device__ float g_keys[BATCH*SEQ*HID];
__device__ float g_q[BH];
__device__ float g_context[BH];
__device__ float g_ctx[BH];
__device__ float g_h[2*4*BH];
__device__ float g_hs[NSTEP*BH];
__device__ float g_part[6*3*BH];
__device__ float g_w2[VOCAB*HID];                  // tf32 fc2 weights
#define WG_TOT (1536*1536 + 3*1536*1024)
__device__ float g_wgh[WG_TOT];                    // GRU packed [wih|whh] hi
__device__ float g_wgl[WG_TOT];                    // lo
__device__ float g_wqh[HID*HID], g_wql[HID*HID];   // wq hi/lo
__device__ float g_f0h[HID*HID], g_f0l[HID*HID];   // fc0 hi/lo
__device__ int   g_cnt[8];

__device__ __forceinline__ float rtf32(float x) {
    uint32_t r; asm("cvt.rna.tf32.f32 %0, %1;" : "=r"(r) : "f"(x));
    return __uint_as_float(r);
}
__device__ __forceinline__ void split32(float v, float& h, float& l) {
    h = rtf32(v); l = rtf32(v - h);
}
__device__ __forceinline__ void hmma_tf32(float& c0, float& c1, float& c2, float& c3,
                                          uint32_t a0, uint32_t a1, uint32_t a2, uint32_t a3,
                                          uint32_t b0, uint32_t b1) {
    asm volatile("mma.sync.aligned.m16n8k8.row.col.f32.tf32.tf32.f32 "
                 "{%0,%1,%2,%3}, {%4,%5,%6,%7}, {%8,%9}, {%0,%1,%2,%3};"
                 : "+f"(c0), "+f"(c1), "+f"(c2), "+f"(c3)
                 : "r"(a0), "r"(a1), "r"(a2), "r"(a3), "r"(b0), "r"(b1));
}

// ---------------- init ----------------
__global__ void init_kernel() {
    int idx = blockIdx.x * 256 + threadIdx.x;
    if (idx < 4*BH) g_h[idx] = 0.f;
    if (blockIdx.x == 0 && threadIdx.x < 8) g_cnt[threadIdx.x] = 0;
}

// ---------------- weight conversion kernels ----------------
__global__ void cvt_w2_kernel(const float* __restrict__ w) {
    int i = blockIdx.x * 256 + threadIdx.x;
    float4 v = ((const float4*)w)[i];
    float4 r;
    r.x = rtf32(v.x); r.y = rtf32(v.y); r.z = rtf32(v.z); r.w = rtf32(v.w);
    ((float4*)g_w2)[i] = r;
}

__global__ void wsplit_plain(float* __restrict__ dh, float* __restrict__ dl,
                             const float* __restrict__ src, int n4) {
    int i = blockIdx.x * 256 + threadIdx.x;
    if (i >= n4) return;
    float4 v = ((const float4*)src)[i];
    float4 h, l;
    split32(v.x, h.x, l.x); split32(v.y, h.y, l.y);
    split32(v.z, h.z, l.z); split32(v.w, h.w, l.w);
    ((float4*)dh)[i] = h; ((float4*)dl)[i] = l;
}

// pack [wih | whh] rows (1536) x Ktot, split hi/lo
__global__ void wsplit_gru(float* __restrict__ dh, float* __restrict__ dl,
                           const float* __restrict__ wih, const float* __restrict__ whh,
                           int Kin, int Ktot) {
    int i = blockIdx.x * 256 + threadIdx.x;
    int k4 = Ktot >> 2;
    int row = i / k4;
    if (row >= 1536) return;
    int c4 = (i - row * k4) * 4;
    float4 v;
    if (c4 < Kin) v = *(const float4*)(wih + (size_t)row * Kin + c4);
    else          v = *(const float4*)(whh + (size_t)row * 512 + (c4 - Kin));
    float4 h, l;
    split32(v.x, h.x, l.x); split32(v.y, h.y, l.y);
    split32(v.z, h.z, l.z); split32(v.w, h.w, l.w);
    *(float4*)(dh + (size_t)row * Ktot + c4) = h;
    *(float4*)(dl + (size_t)row * Ktot + c4) = l;
}

// ---------------- big SIMT GEMM (precompute, fp32 exact) ----------------
template<int AMODE>
__global__ void gemm_big(const float* __restrict__ A, const float* __restrict__ W,
                         const float* __restrict__ bias, float* __restrict__ C,
                         int ldN, int Kd, const int* __restrict__ caps)
{
    __shared__ float As[8][132];
    __shared__ float Bs[8][132];
    const int tid = threadIdx.x;
    const int bm = blockIdx.y * 128;
    const int bn = blockIdx.x * 128;
    const int tx = tid & 15, ty = tid >> 4;
    const int arow = tid >> 1;
    const int acol = (tid & 1) * 4;

    const float* a_row_ptr;
    if (AMODE == 1) {
        int m = bm + arow;
        int bb = m / NSTEP, tt = m - bb * NSTEP;
        a_row_ptr = A + (size_t)caps[bb * 16 + tt] * Kd;
    } else {
        a_row_ptr = A + (size_t)(bm + arow) * Kd;
    }
    const float* w_row_ptr = W + (size_t)(bn + arow) * Kd;

    float acc[8][8];
    #pragma unroll
    for (int i = 0; i < 8; i++)
        #pragma unroll
        for (int j = 0; j < 8; j++) acc[i][j] = 0.f;

    for (int k0 = 0; k0 < Kd; k0 += 8) {
        float4 av = *(const float4*)(a_row_ptr + k0 + acol);
        float4 wv = *(const float4*)(w_row_ptr + k0 + acol);
        As[acol+0][arow] = av.x; As[acol+1][arow] = av.y;
        As[acol+2][arow] = av.z; As[acol+3][arow] = av.w;
        Bs[acol+0][arow] = wv.x; Bs[acol+1][arow] = wv.y;
        Bs[acol+2][arow] = wv.z; Bs[acol+3][arow] = wv.w;
        __syncthreads();
        #pragma unroll
        for (int k = 0; k < 8; k++) {
            float af[8], bf[8];
            *(float4*)&af[0] = *(const float4*)&As[k][ty*8];
            *(float4*)&af[4] = *(const float4*)&As[k][ty*8+4];
            *(float4*)&bf[0] = *(const float4*)&Bs[k][tx*8];
            *(float4*)&bf[4] = *(const float4*)&Bs[k][tx*8+4];
            #pragma unroll
            for (int i = 0; i < 8; i++)
                #pragma unroll
                for (int j = 0; j < 8; j++)
                    acc[i][j] += af[i] * bf[j];
        }
        __syncthreads();
    }
    #pragma unroll
    for (int i = 0; i < 8; i++) {
        int m = bm + ty*8 + i;
        float* cptr = C + (size_t)m * ldN + bn + tx*8;
        #pragma unroll
        for (int j = 0; j < 8; j += 4) {
            float4 v;
            v.x = acc[i][j+0] + bias[bn + tx*8 + j+0];
            v.y = acc[i][j+1] + bias[bn + tx*8 + j+1];
            v.z = acc[i][j+2] + bias[bn + tx*8 + j+2];
            v.w = acc[i][j+3] + bias[bn + tx*8 + j+3];
            *(float4*)(cptr + j) = v;
        }
    }
}

// =====================================================================
// Small 3xTF32 GEMM: C[128x512] = A[128x512] @ W^T + bias
// grid 8 (BN=64), 256 threads, K=512.  W pre-split hi/lo.
// =====================================================================
#define SG_SMEM ((2*4608*2 + 2*2304*2)*4)

__global__ void __launch_bounds__(256, 1) sg_mma(
    const float* __restrict__ A,
    const float* __restrict__ Wh, const float* __restrict__ Wl,
    const float* __restrict__ bias, float* __restrict__ C)
{
    extern __shared__ float sm[];
    float* AH = sm;              // [2][128*36]
    float* AL = AH + 2*4608;
    float* BHs = AL + 2*4608;    // [2][64*36]
    float* BLs = BHs + 2*2304;

    const int tid = threadIdx.x;
    const int lane = tid & 31, wid = tid >> 5;
    const int wm = (wid & 1) * 64;
    const int wn = (wid >> 1) * 16;
    const int grp = lane >> 2, tig = lane & 3;
    const int bn = blockIdx.x * 64;

    const int lrow = tid >> 3;
    const int lc4  = (tid & 7) * 4;

    float acc[4][2][4];
    #pragma unroll
    for (int i = 0; i < 4; i++)
        #pragma unroll
        for (int j = 0; j < 2; j++)
            #pragma unroll
            for (int k = 0; k < 4; k++) acc[i][j][k] = 0.f;

    float4 ra[4], rbh[2], rbl[2];
    #pragma unroll
    for (int p = 0; p < 4; p++)
        ra[p] = *(const float4*)(A + (size_t)(p*32 + lrow) * 512 + lc4);
    #pragma unroll
    for (int p = 0; p < 2; p++) {
        rbh[p] = *(const float4*)(Wh + (size_t)(bn + p*32 + lrow) * 512 + lc4);
        rbl[p] = *(const float4*)(Wl + (size_t)(bn + p*32 + lrow) * 512 + lc4);
    }
    #pragma unroll
    for (int p = 0; p < 4; p++) {
        float4 h, l;
        split32(ra[p].x, h.x, l.x); split32(ra[p].y, h.y, l.y);
        split32(ra[p].z, h.z, l.z); split32(ra[p].w, h.w, l.w);
        *(float4*)(AH + (p*32 + lrow)*GPAD + lc4) = h;
        *(float4*)(AL + (p*32 + lrow)*GPAD + lc4) = l;
    }
    #pragma unroll
    for (int p = 0; p < 2; p++) {
        *(float4*)(BHs + (p*32 + lrow)*GPAD + lc4) = rbh[p];
        *(float4*)(BLs + (p*32 + lrow)*GPAD + lc4) = rbl[p];
    }
    __syncthreads();

    #pragma unroll 1
    for (int kt = 0; kt < 16; kt++) {
        const int buf = kt & 1;
        const float* Ah = AH + buf * 4608;
        const float* Al = AL + buf * 4608;
        const float* Bh = BHs + buf * 2304;
        const float* Bl = BLs + buf * 2304;

        if (kt < 15) {
            int co = (kt + 1) * 32 + lc4;
            #pragma unroll
            for (int p = 0; p < 4; p++)
                ra[p] = *(const float4*)(A + (size_t)(p*32 + lrow) * 512 + co);
            #pragma unroll
            for (int p = 0; p < 2; p++) {
                rbh[p] = *(const float4*)(Wh + (size_t)(bn + p*32 + lrow) * 512 + co);
                rbl[p] = *(const float4*)(Wl + (size_t)(bn + p*32 + lrow) * 512 + co);
            }
        }

        #pragma unroll
        for (int k8 = 0; k8 < 4; k8++) {
            const int kc = k8*8 + tig;
            uint32_t ah[4][4], al[4][4];
            #pragma unroll
            for (int mi = 0; mi < 4; mi++) {
                const float* arh = Ah + (wm + mi*16 + grp)*GPAD;
                const float* arl = Al + (wm + mi*16 + grp)*GPAD;
                ah[mi][0] = __float_as_uint(arh[kc]);
                ah[mi][1] = __float_as_uint(arh[8*GPAD + kc]);
                ah[mi][2] = __float_as_uint(arh[kc + 4]);
                ah[mi][3] = __float_as_uint(arh[8*GPAD + kc + 4]);
                al[mi][0] = __float_as_uint(arl[kc]);
                al[mi][1] = __float_as_uint(arl[8*GPAD + kc]);
                al[mi][2] = __float_as_uint(arl[kc + 4]);
                al[mi][3] = __float_as_uint(arl[8*GPAD + kc + 4]);
            }
            #pragma unroll
            for (int nj = 0; nj < 2; nj++) {
                const float* brh = Bh + (wn + nj*8 + grp)*GPAD + k8*8;
                const float* brl = Bl + (wn + nj*8 + grp)*GPAD + k8*8;
                uint32_t b0h = __float_as_uint(brh[tig]);
                uint32_t b1h = __float_as_uint(brh[tig + 4]);
                uint32_t b0l = __float_as_uint(brl[tig]);
                uint32_t b1l = __float_as_uint(brl[tig + 4]);
                #pragma unroll
                for (int mi = 0; mi < 4; mi++) {
                    hmma_tf32(acc[mi][nj][0], acc[mi][nj][1], acc[mi][nj][2], acc[mi][nj][3],
                              ah[mi][0], ah[mi][1], ah[mi][2], ah[mi][3], b0h, b1h);
                    hmma_tf32(acc[mi][nj][0], acc[mi][nj][1], acc[mi][nj][2], acc[mi][nj][3],
                              ah[mi][0], ah[mi][1], ah[mi][2], ah[mi][3], b0l, b1l);
                    hmma_tf32(acc[mi][nj][0], acc[mi][nj][1], acc[mi][nj][2], acc[mi][nj][3],
                              al[mi][0], al[mi][1], al[mi][2], al[mi][3], b0h, b1h);
                }
            }
        }

        if (kt < 15) {
            float* Ahn = AH + (buf ^ 1) * 4608;
            float* Aln = AL + (buf ^ 1) * 4608;
            float* Bhn = BHs + (buf ^ 1) * 2304;
            float* Bln = BLs + (buf ^ 1) * 2304;
            #pragma unroll
            for (int p = 0; p < 4; p++) {
                float4 h, l;
                split32(ra[p].x, h.x, l.x); split32(ra[p].y, h.y, l.y);
                split32(ra[p].z, h.z, l.z); split32(ra[p].w, h.w, l.w);
                *(float4*)(Ahn + (p*32 + lrow)*GPAD + lc4) = h;
                *(float4*)(Aln + (p*32 + lrow)*GPAD + lc4) = l;
            }
            #pragma unroll
            for (int p = 0; p < 2; p++) {
                *(float4*)(Bhn + (p*32 + lrow)*GPAD + lc4) = rbh[p];
                *(float4*)(Bln + (p*32 + lrow)*GPAD + lc4) = rbl[p];
            }
        }
        __syncthreads();
    }

    #pragma unroll
    for (int mi = 0; mi < 4; mi++) {
        #pragma unroll
        for (int nj = 0; nj < 2; nj++) {
            int m = wm + mi*16 + grp;
            int n = bn + wn + nj*8 + tig*2;
            float bx = bias[n], by = bias[n+1];
            *(float2*)(C + (size_t)m * 512 + n) =
                make_float2(acc[mi][nj][0] + bx, acc[mi][nj][1] + by);
            *(float2*)(C + (size_t)(m+8) * 512 + n) =
                make_float2(acc[mi][nj][2] + bx, acc[mi][nj][3] + by);
        }
    }
}

// =====================================================================
// Fused GRU layer: 3xTF32 MMA + K-split + last-block gate fusion.
// grid (24 n-tiles of 64 over 1536, NK k-chunks of 512), 256 threads.
// chunk sources: kc=0 -> srcA(ldA), kc=1 -> srcB, kc=2 -> srcC. h-side = last.
// =====================================================================
template<int NK>
__global__ void __launch_bounds__(256, 1) gru_mma(
    const float* __restrict__ srcA, int ldA,
    const float* __restrict__ srcB, const float* __restrict__ srcC,
    const float* __restrict__ Wh, const float* __restrict__ Wl, int ldK,
    const float* __restrict__ bih, const float* __restrict__ bhh,
    const float* __restrict__ h_old, float* __restrict__ h_new,
    float* __restrict__ hs_out)
{
    extern __shared__ float sm[];
    float* AH = sm;
    float* AL = AH + 2*4608;
    float* BHs = AL + 2*4608;
    float* BLs = BHs + 2*2304;

    const int tid = threadIdx.x;
    const int lane = tid & 31, wid = tid >> 5;
    const int wm = (wid & 1) * 64;
    const int wn = (wid >> 1) * 16;
    const int grp = lane >> 2, tig = lane & 3;
    const int nt = blockIdx.x;
    const int kc = blockIdx.y;
    const int bn = nt * 64;

    const float* src; int ld;
    if (kc == 0)      { src = srcA; ld = ldA; }
    else if (kc == 1) { src = srcB; ld = 512; }
    else              { src = srcC; ld = 512; }

    const int lrow = tid >> 3;
    const int lc4  = (tid & 7) * 4;
    const size_t wko = (size_t)kc * 512;

    float acc[4][2][4];
    #pragma unroll
    for (int i = 0; i < 4; i++)
        #pragma unroll
        for (int j = 0; j < 2; j++)
            #pragma unroll
            for (int k = 0; k < 4; k++) acc[i][j][k] = 0.f;

    float4 ra[4], rbh[2], rbl[2];
    #pragma unroll
    for (int p = 0; p < 4; p++)
        ra[p] = *(const float4*)(src + (size_t)(p*32 + lrow) * ld + lc4);
    #pragma unroll
    for (int p = 0; p < 2; p++) {
        rbh[p] = *(const float4*)(Wh + (size_t)(bn + p*32 + lrow) * ldK + wko + lc4);
        rbl[p] = *(const float4*)(Wl + (size_t)(bn + p*32 + lrow) * ldK + wko + lc4);
    }
    #pragma unroll
    for (int p = 0; p < 4; p++) {
        float4 h, l;
        split32(ra[p].x, h.x, l.x); split32(ra[p].y, h.y, l.y);
        split32(ra[p].z, h.z, l.z); split32(ra[p].w, h.w, l.w);
        *(float4*)(AH + (p*32 + lrow)*GPAD + lc4) = h;
        *(float4*)(AL + (p*32 + lrow)*GPAD + lc4) = l;
    }
    #pragma unroll
    for (int p = 0; p < 2; p++) {
        *(float4*)(BHs + (p*32 + lrow)*GPAD + lc4) = rbh[p];
        *(float4*)(BLs + (p*32 + lrow)*GPAD + lc4) = rbl[p];
    }
    __syncthreads();

    #pragma unroll 1
    for (int kt = 0; kt < 16; kt++) {
        const int buf = kt & 1;
        const float* Ah = AH + buf * 4608;
        const float* Al = AL + buf * 4608;
        const float* Bh = BHs + buf * 2304;
        const float* Bl = BLs + buf * 2304;

        if (kt < 15) {
            int co = (kt + 1) * 32 + lc4;
            #pragma unroll
            for (int p = 0; p < 4; p++)
                ra[p] = *(const float4*)(src + (size_t)(p*32 + lrow) * ld + co);
            #pragma unroll
            for (int p = 0; p < 2; p++) {
                rbh[p] = *(const float4*)(Wh + (size_t)(bn + p*32 + lrow) * ldK + wko + co);
                rbl[p] = *(const float4*)(Wl + (size_t)(bn + p*32 + lrow) * ldK + wko + co);
            }
        }

        #pragma unroll
        for (int k8 = 0; k8 < 4; k8++) {
            const int kcc = k8*8 + tig;
            uint32_t ah[4][4], al[4][4];
            #pragma unroll
            for (int mi = 0; mi < 4; mi++) {
                const float* arh = Ah + (wm + mi*16 + grp)*GPAD;
                const float* arl = Al + (wm + mi*16 + grp)*GPAD;
                ah[mi][0] = __float_as_uint(arh[kcc]);
                ah[mi][1] = __float_as_uint(arh[8*GPAD + kcc]);
                ah[mi][2] = __float_as_uint(arh[kcc + 4]);
                ah[mi][3] = __float_as_uint(arh[8*GPAD + kcc + 4]);
                al[mi][0] = __float_as_uint(arl[kcc]);
                al[mi][1] = __float_as_uint(arl[8*GPAD + kcc]);
                al[mi][2] = __float_as_uint(arl[kcc + 4]);
                al[mi][3] = __float_as_uint(arl[8*GPAD + kcc + 4]);
            }
            #pragma unroll
            for (int nj = 0; nj < 2; nj++) {
                const float* brh = Bh + (wn + nj*8 + grp)*GPAD + k8*8;
                const float* brl = Bl + (wn + nj*8 + grp)*GPAD + k8*8;
                uint32_t b0h = __float_as_uint(brh[tig]);
                uint32_t b1h = __float_as_uint(brh[tig + 4]);
                uint32_t b0l = __float_as_uint(brl[tig]);
                uint32_t b1l = __float_as_uint(brl[tig + 4]);
                #pragma unroll
                for (int mi = 0; mi < 4; mi++) {
                    hmma_tf32(acc[mi][nj][0], acc[mi][nj][1], acc[mi][nj][2], acc[mi][nj][3],
                              ah[mi][0], ah[mi][1], ah[mi][2], ah[mi][3], b0h, b1h);
                    hmma_tf32(acc[mi][nj][0], acc[mi][nj][1], acc[mi][nj][2], acc[mi][nj][3],
                              ah[mi][0], ah[mi][1], ah[mi][2], ah[mi][3], b0l, b1l);
                    hmma_tf32(acc[mi][nj][0], acc[mi][nj][1], acc[mi][nj][2], acc[mi][nj][3],
                              al[mi][0], al[mi][1], al[mi][2], al[mi][3], b0h, b1h);
                }
            }
        }

        if (kt < 15) {
            float* Ahn = AH + (buf ^ 1) * 4608;
            float* Aln = AL + (buf ^ 1) * 4608;
            float* Bhn = BHs + (buf ^ 1) * 2304;
            float* Bln = BLs + (buf ^ 1) * 2304;
            #pragma unroll
            for (int p = 0; p < 4; p++) {
                float4 h, l;
                split32(ra[p].x, h.x, l.x); split32(ra[p].y, h.y, l.y);
                split32(ra[p].z, h.z, l.z); split32(ra[p].w, h.w, l.w);
                *(float4*)(Ahn + (p*32 + lrow)*GPAD + lc4) = h;
                *(float4*)(Aln + (p*32 + lrow)*GPAD + lc4) = l;
            }
            #pragma unroll
            for (int p = 0; p < 2; p++) {
                *(float4*)(Bhn + (p*32 + lrow)*GPAD + lc4) = rbh[p];
                *(float4*)(Bln + (p*32 + lrow)*GPAD + lc4) = rbl[p];
            }
        }
        __syncthreads();
    }

    // write partial tile
    {
        float* P = g_part + ((size_t)(kc*24 + nt)) * 8192;
        #pragma unroll
        for (int mi = 0; mi < 4; mi++) {
            #pragma unroll
            for (int nj = 0; nj < 2; nj++) {
                int m = wm + mi*16 + grp;
                int nc = wn + nj*8 + tig*2;
                *(float2*)(P + m*64 + nc)     = make_float2(acc[mi][nj][0], acc[mi][nj][1]);
                *(float2*)(P + (m+8)*64 + nc) = make_float2(acc[mi][nj][2], acc[mi][nj][3]);
            }
        }
    }

    __threadfence();
    __shared__ int sdone;
    if (tid == 0) {
        int g = nt & 7;
        int v = atomicAdd(&g_cnt[g], 1);
        int done = (v == 3*NK - 1);
        if (done) g_cnt[g] = 0;
        sdone = done;
    }
    __syncthreads();
    if (!sdone) return;

    // ---- gate epilogue (finisher block) ----
    const int g = nt & 7;
    const int cc = (tid & 15) * 4;
    const int c  = g*64 + cc;
    float4 bir = *(const float4*)(bih + c);
    float4 biz = *(const float4*)(bih + 512 + c);
    float4 bin = *(const float4*)(bih + 1024 + c);
    float4 bhr = *(const float4*)(bhh + c);
    float4 bhz = *(const float4*)(bhh + 512 + c);
    float4 bhn = *(const float4*)(bhh + 1024 + c);

    #pragma unroll
    for (int i = 0; i < 8; i++) {
        const int m = (tid >> 4) * 8 + i;
        float4 r4 = make_float4(0,0,0,0), z4 = r4, in4 = r4, hn4 = r4;
        #pragma unroll
        for (int kx = 0; kx < NK; kx++) {
            const float* Pr = g_part + ((size_t)(kx*24 + g))      * 8192 + m*64 + cc;
            const float* Pz = g_part + ((size_t)(kx*24 + 8 + g))  * 8192 + m*64 + cc;
            const float* Pn = g_part + ((size_t)(kx*24 + 16 + g)) * 8192 + m*64 + cc;
            float4 a = *(const float4*)Pr; r4.x += a.x; r4.y += a.y; r4.z += a.z; r4.w += a.w;
            a = *(const float4*)Pz;        z4.x += a.x; z4.y += a.y; z4.z += a.z; z4.w += a.w;
            a = *(const float4*)Pn;
            if (kx < NK-1) { in4.x += a.x; in4.y += a.y; in4.z += a.z; in4.w += a.w; }
            else           { hn4.x += a.x; hn4.y += a.y; hn4.z += a.z; hn4.w += a.w; }
        }
        float4 ho = *(const float4*)(h_old + (size_t)m*512 + c);
        float hv[4];
        #pragma unroll
        for (int q = 0; q < 4; q++) {
            float rp = ((float*)&r4)[q] + ((float*)&bir)[q] + ((float*)&bhr)[q];
            float zp = ((float*)&z4)[q] + ((float*)&biz)[q] + ((float*)&bhz)[q];
            float ip = ((float*)&in4)[q] + ((float*)&bin)[q];
            float hp = ((float*)&hn4)[q] + ((float*)&bhn)[q];
            float r = 1.f / (1.f + expf(-rp));
            float z = 1.f / (1.f + expf(-zp));
            float n = tanhf(ip + r * hp);
            hv[q] = (1.f - z) * n + z * ((float*)&ho)[q];
        }
        *(float4*)(h_new + (size_t)m*512 + c) = make_float4(hv[0], hv[1], hv[2], hv[3]);
        if (hs_out) {
            *(float4*)(hs_out + (size_t)m*512 + c) =
                make_float4(rtf32(hv[0]), rtf32(hv[1]), rtf32(hv[2]), rtf32(hv[3]));
        }
    }
}

// ---------------- attention: energies + softmax + context ----------------
__global__ void att_kernel(const float* __restrict__ q, const float* __restrict__ keys,
                           const float* __restrict__ features, const float* __restrict__ v_w,
                           float* __restrict__ ctx_out)
{
    const int b = blockIdx.x;
    const int tid = threadIdx.x;   // 256
    __shared__ float qs[512], vw[512], e[64];

    for (int i = tid; i < 512; i += 256) { qs[i] = q[b*512 + i]; vw[i] = v_w[i]; }
    __syncthreads();

    const int warp = tid >> 5, lane = tid & 31;
    for (int s = warp; s < SEQ; s += 8) {
        const float* kp = keys + ((size_t)b * SEQ + s) * 512;
        float acc = 0.f;
        #pragma unroll
        for (int k = lane; k < 512; k += 32)
            acc += tanhf(qs[k] + kp[k]) * vw[k];
        #pragma unroll
        for (int o = 16; o; o >>= 1) acc += __shfl_xor_sync(0xffffffffu, acc, o);
        if (!lane) e[s] = acc;
    }
    __syncthreads();

    if (warp == 0) {
        float v1 = (lane < SEQ) ? e[lane] : -1e30f;
        float v2 = (lane + 32 < SEQ) ? e[lane + 32] : -1e30f;
        float m = fmaxf(v1, v2);
        #pragma unroll
        for (int o = 16; o; o >>= 1) m = fmaxf(m, __shfl_xor_sync(0xffffffffu, m, o));
        float e1 = (lane < SEQ) ? expf(v1 - m) : 0.f;
        float e2 = (lane + 32 < SEQ) ? expf(v2 - m) : 0.f;
        float s = e1 + e2;
        #pragma unroll
        for (int o = 16; o; o >>= 1) s += __shfl_xor_sync(0xffffffffu, s, o);
        float inv = 1.f / s;
        if (lane < SEQ) e[lane] = e1 * inv;
        if (lane + 32 < SEQ) e[lane + 32] = e2 * inv;
    }
    __syncthreads();

    for (int k = tid; k < 512; k += 256) {
        float acc = 0.f;
        const float* f = features + (size_t)b * SEQ * 512 + k;
        #pragma unroll 7
        for (int s = 0; s < SEQ; s++) acc += e[s] * f[(size_t)s * 512];
        ctx_out[b*512 + k] = acc;
    }
}

// ---------------- fc2 via mma.sync tf32 (unchanged) ----------------
#define FC2_PAD   36
#define FC2_ASZ   (128*FC2_PAD)
#define FC2_BSZ   (256*FC2_PAD)
#define FC2_SMEM  ((2*FC2_ASZ + 2*FC2_BSZ)*4)

__global__ void __launch_bounds__(256, 1) fc2_mma(
    const float* __restrict__ A, const float* __restrict__ Bw,
    const float* __restrict__ bias, float* __restrict__ out)
{
    extern __shared__ float smf[];
    float* As = smf;
    float* Bs = smf + 2*FC2_ASZ;

    const int tid  = threadIdx.x;
    const int lane = tid & 31, wid = tid >> 5;
    const int wm = (wid >> 2) * 64;
    const int wn = (wid & 3)  * 64;
    const int grp = lane >> 2;
    const int tig = lane & 3;
    const int bn = blockIdx.x * 256;
    const int t  = blockIdx.y;

    const float* Ab = A  + (size_t)t  * 128 * 512;
    const float* Bb = Bw + (size_t)bn * 512;

    const int lrowA = tid >> 3;
    const int lc4   = (tid & 7) * 4;

    float acc[4][8][4];
    #pragma unroll
    for (int i = 0; i < 4; i++)
        #pragma unroll
        for (int j = 0; j < 8; j++)
            #pragma unroll
            for (int k = 0; k < 4; k++) acc[i][j][k] = 0.f;

    float4 ra[4], rb[8];
    #pragma unroll
    for (int p = 0; p < 4; p++)
        ra[p] = *(const float4*)(Ab + (size_t)(p*32 + lrowA) * 512 + lc4);
    #pragma unroll
    for (int p = 0; p < 8; p++)
        rb[p] = *(const float4*)(Bb + (size_t)(p*32 + lrowA) * 512 + lc4);
    #pragma unroll
    for (int p = 0; p < 4; p++)
        *(float4*)(As + (p*32 + lrowA)*FC2_PAD + lc4) = ra[p];
    #pragma unroll
    for (int p = 0; p < 8; p++)
        *(float4*)(Bs + (p*32 + lrowA)*FC2_PAD + lc4) = rb[p];
    __syncthreads();

    #pragma unroll 1
    for (int kt = 0; kt < 16; kt++) {
        const int buf = kt & 1;
        const float* Asb = As + buf * FC2_ASZ;
        const float* Bsb = Bs + buf * FC2_BSZ;

        if (kt < 15) {
            const float* Aq = Ab + (kt+1)*32;
            const float* Bq = Bb + (kt+1)*32;
            #pragma unroll
            for (int p = 0; p < 4; p++)
                ra[p] = *(const float4*)(Aq + (size_t)(p*32 + lrowA) * 512 + lc4);
            #pragma unroll
            for (int p = 0; p < 8; p++)
                rb[p] = *(const float4*)(Bq + (size_t)(p*32 + lrowA) * 512 + lc4);
        }

        #pragma unroll
        for (int k8 = 0; k8 < 4; k8++) {
            const int kc = k8*8 + tig;
            uint32_t af[4][4];
            #pragma unroll
            for (int mi = 0; mi < 4; mi++) {
                const float* ar = Asb + (wm + mi*16 + grp)*FC2_PAD;
                af[mi][0] = __float_as_uint(ar[kc]);
                af[mi][1] = __float_as_uint(ar[8*FC2_PAD + kc]);
                af[mi][2] = __float_as_uint(ar[kc + 4]);
                af[mi][3] = __float_as_uint(ar[8*FC2_PAD + kc + 4]);
            }
            #pragma unroll
            for (int nj = 0; nj < 8; nj++) {
                const float* br = Bsb + (wn + nj*8 + grp)*FC2_PAD + k8*8;
                uint32_t b0 = __float_as_uint(br[tig]);
                uint32_t b1 = __float_as_uint(br[tig + 4]);
                #pragma unroll
                for (int mi = 0; mi < 4; mi++)
                    hmma_tf32(acc[mi][nj][0], acc[mi][nj][1], acc[mi][nj][2], acc[mi][nj][3],
                              af[mi][0], af[mi][1], af[mi][2], af[mi][3], b0, b1);
            }
        }

        if (kt < 15) {
            float* Asn = As + (buf ^ 1) * FC2_ASZ;
            float* Bsn = Bs + (buf ^ 1) * FC2_BSZ;
            #pragma unroll
            for (int p = 0; p < 4; p++)
                *(float4*)(Asn + (p*32 + lrowA)*FC2_PAD + lc4) = ra[p];
            #pragma unroll
            for (int p = 0; p < 8; p++)
                *(float4*)(Bsn + (p*32 + lrowA)*FC2_PAD + lc4) = rb[p];
        }
        __syncthreads();
    }

    #pragma unroll
    for (int mi = 0; mi < 4; mi++) {
        const int b0 = wm + mi*16 + grp;
        float* o0 = out + ((size_t)b0       * NSTEP + t) * VOCAB + bn + wn;
        float* o8 = out + ((size_t)(b0 + 8) * NSTEP + t) * VOCAB + bn + wn;
        #pragma unroll
        for (int nj = 0; nj < 8; nj++) {
            const int n = nj*8 + 2*tig;
            float bx = bias[bn + wn + n];
            float by = bias[bn + wn + n + 1];
            *(float2*)(o0 + n) = make_float2(acc[mi][nj][0] + bx, acc[mi][nj][1] + by);
            *(float2*)(o8 + n) = make_float2(acc[mi][nj][2] + bx, acc[mi][nj][3] + by);
        }
    }
}

// ---------------- host launch ----------------
extern "C" void kernel_launch(void* const* d_in, const int* in_sizes, int n_in,
                              void* d_out, int out_size)
{
    const float* features = (const float*)d_in[0];
    const int*   caps     = (const int*)  d_in[1];
    const float* emb      = (const float*)d_in[2];
    const float* fc1_w    = (const float*)d_in[3];
    const float* fc1_b    = (const float*)d_in[4];
    const float* fc0_w    = (const float*)d_in[5];
    const float* fc0_b    = (const float*)d_in[6];
    const float* wq       = (const float*)d_in[7];
    const float* bq       = (const float*)d_in[8];
    const float* wk       = (const float*)d_in[9];
    const float* bk       = (const float*)d_in[10];
    const float* v_w      = (const float*)d_in[11];
    const float* wih0     = (const float*)d_in[13];
    const float* whh0     = (const float*)d_in[14];
    const float* bih0     = (const float*)d_in[15];
    const float* bhh0     = (const float*)d_in[16];
    const float* wihr     = (const float*)d_in[17];
    const float* whhr     = (const float*)d_in[18];
    const float* bihr     = (const float*)d_in[19];
    const float* bhhr     = (const float*)d_in[20];
    const float* fc2_w    = (const float*)d_in[21];
    const float* fc2_b    = (const float*)d_in[22];
    float* out = (float*)d_out;

    float *px, *pkeys, *pq, *pcontext, *pctx, *ph, *phs, *pw2;
    float *pwgh, *pwgl, *pwqh, *pwql, *pf0h, *pf0l;
    cudaGetSymbolAddress((void**)&px,       g_x);
    cudaGetSymbolAddress((void**)&pkeys,    g_keys);
    cudaGetSymbolAddress((void**)&pq,       g_q);
    cudaGetSymbolAddress((void**)&pcontext, g_context);
    cudaGetSymbolAddress((void**)&pctx,     g_ctx);
    cudaGetSymbolAddress((void**)&ph,       g_h);
    cudaGetSymbolAddress((void**)&phs,      g_hs);
    cudaGetSymbolAddress((void**)&pw2,      g_w2);
    cudaGetSymbolAddress((void**)&pwgh,     g_wgh);
    cudaGetSymbolAddress((void**)&pwgl,     g_wgl);
    cudaGetSymbolAddress((void**)&pwqh,     g_wqh);
    cudaGetSymbolAddress((void**)&pwql,     g_wql);
    cudaGetSymbolAddress((void**)&pf0h,     g_f0h);
    cudaGetSymbolAddress((void**)&pf0l,     g_f0l);

    cudaFuncSetAttribute(fc2_mma, cudaFuncAttributeMaxDynamicSharedMemorySize, FC2_SMEM);
    cudaFuncSetAttribute(sg_mma,  cudaFuncAttributeMaxDynamicSharedMemorySize, SG_SMEM);
    cudaFuncSetAttribute(gru_mma<2>, cudaFuncAttributeMaxDynamicSharedMemorySize, SG_SMEM);
    cudaFuncSetAttribute(gru_mma<3>, cudaFuncAttributeMaxDynamicSharedMemorySize, SG_SMEM);

    init_kernel<<<1024, 256>>>();
    cvt_w2_kernel<<<VOCAB*HID/4/256, 256>>>(fc2_w);

    // split weights
    wsplit_plain<<<(HID*HID/4 + 255)/256, 256>>>(pwqh, pwql, wq, HID*HID/4);
    wsplit_plain<<<(HID*HID/4 + 255)/256, 256>>>(pf0h, pf0l, fc0_w, HID*HID/4);
    wsplit_gru<<<(1536*1536/4 + 255)/256, 256>>>(pwgh, pwgl, wih0, whh0, 1024, 1536);
    for (int l = 1; l < 4; l++) {
        size_t off = (size_t)1536*1536 + (size_t)(l-1)*1536*1024;
        wsplit_gru<<<(1536*1024/4 + 255)/256, 256>>>(
            pwgh + off, pwgl + off,
            wihr + (size_t)(l-1)*1536*512, whhr + (size_t)(l-1)*1536*512, 512, 1024);
    }

    gemm_big<1><<<dim3(4, 15), 256>>>(emb, fc1_w, fc1_b, px, 512, 512, caps);
    gemm_big<0><<<dim3(4, 49), 256>>>(features, wk, bk, pkeys, 512, 512, nullptr);

    for (int t = 0; t < NSTEP; t++) {
        const float* hold = ph + (t & 1) * (4 * BH);
        float*       hnew = ph + ((t & 1) ^ 1) * (4 * BH);

        // q = h3 @ wq^T + bq
        sg_mma<<<8, 256, SG_SMEM>>>(hold + 3 * BH, pwqh, pwql, bq, pq);
        // attention -> raw context
        att_kernel<<<128, 256>>>(pq, pkeys, features, v_w, pcontext);
        // ctx = context @ fc0^T + fc0_b
        sg_mma<<<8, 256, SG_SMEM>>>(pcontext, pf0h, pf0l, fc0_b, pctx);

        // layer 0: chunks x, ctx, h
        gru_mma<3><<<dim3(24, 3), 256, SG_SMEM>>>(
            px + t * HID, NSTEP * HID, pctx, hold,
            pwgh, pwgl, 1536, bih0, bhh0, hold, hnew, nullptr);

        for (int l = 1; l < 4; l++) {
            size_t off = (size_t)1536*1536 + (size_t)(l-1)*1536*1024;
            gru_mma<2><<<dim3(24, 2), 256, SG_SMEM>>>(
                hnew + (l-1) * BH, 512, hold + l * BH, nullptr,
                pwgh + off, pwgl + off, 1024,
                bihr + (l-1) * 1536, bhhr + (l-1) * 1536,
                hold + l * BH, hnew + l * BH,
                (l == 3) ? (phs + t * BH) : nullptr);
        }
    }

    fc2_mma<<<dim3(VOCAB/256, NSTEP), 256, FC2_SMEM>>>(phs, pw2, fc2_b, out);
}

// round 5
// speedup vs baseline: 1.1989x; 1.1989x over previous
#include <cuda_runtime.h>
#include <cuda_fp16.h>
#include <math.h>
#include <cstdint>

#define BATCH 128
#define SEQ   49
#define HID   512
#define VOCAB 32000
#define NSTEP 15
#define BH    (BATCH*HID)

// ---------------- device scratch ----------------
__device__ float  g_x[BATCH*NSTEP*HID];
__device__ float  g_keys[BATCH*SEQ*HID];
__device__ float  g_ctx[BH];
__device__ float  g_h[2*4*BH];
__device__ __half g_hsh[NSTEP*BH];          // fp16 top-layer h (fc2 A operand)
__device__ float  g_part[6*3*BH];
__device__ __half g_w2h[VOCAB*HID];         // fp16 fc2 weights

// ---------------- init ----------------
__global__ void init_kernel() {
    int idx = blockIdx.x * 256 + threadIdx.x;
    if (idx < 4*BH) g_h[idx] = 0.f;
}

// ---------------- fc2 weights -> fp16 ----------------
__global__ void cvt_w2_kernel(const float* __restrict__ w) {
    int i = blockIdx.x * 256 + threadIdx.x;          // 8 floats per thread
    const float4* in = (const float4*)w;
    float4 v0 = in[2*i], v1 = in[2*i + 1];
    __half2 h0 = __floats2half2_rn(v0.x, v0.y);
    __half2 h1 = __floats2half2_rn(v0.z, v0.w);
    __half2 h2 = __floats2half2_rn(v1.x, v1.y);
    __half2 h3 = __floats2half2_rn(v1.z, v1.w);
    uint4 o;
    o.x = *(uint32_t*)&h0; o.y = *(uint32_t*)&h1;
    o.z = *(uint32_t*)&h2; o.w = *(uint32_t*)&h3;
    ((uint4*)g_w2h)[i] = o;
}

// ---------------- big SIMT GEMM (x precompute, fp32 exact) ----------------
template<int AMODE>
__global__ void gemm_big(const float* __restrict__ A, const float* __restrict__ W,
                         const float* __restrict__ bias, float* __restrict__ C,
                         int ldN, int Kd, const int* __restrict__ caps)
{
    __shared__ float As[8][132];
    __shared__ float Bs[8][132];
    const int tid = threadIdx.x;
    const int bm = blockIdx.y * 128;
    const int bn = blockIdx.x * 128;
    const int tx = tid & 15, ty = tid >> 4;
    const int arow = tid >> 1;
    const int acol = (tid & 1) * 4;

    const float* a_row_ptr;
    if (AMODE == 1) {
        int m = bm + arow;
        int bb = m / NSTEP, tt = m - bb * NSTEP;
        a_row_ptr = A + (size_t)caps[bb * 16 + tt] * Kd;
    } else {
        a_row_ptr = A + (size_t)(bm + arow) * Kd;
    }
    const float* w_row_ptr = W + (size_t)(bn + arow) * Kd;

    float acc[8][8];
    #pragma unroll
    for (int i = 0; i < 8; i++)
        #pragma unroll
        for (int j = 0; j < 8; j++) acc[i][j] = 0.f;

    for (int k0 = 0; k0 < Kd; k0 += 8) {
        float4 av = *(const float4*)(a_row_ptr + k0 + acol);
        float4 wv = *(const float4*)(w_row_ptr + k0 + acol);
        As[acol+0][arow] = av.x; As[acol+1][arow] = av.y;
        As[acol+2][arow] = av.z; As[acol+3][arow] = av.w;
        Bs[acol+0][arow] = wv.x; Bs[acol+1][arow] = wv.y;
        Bs[acol+2][arow] = wv.z; Bs[acol+3][arow] = wv.w;
        __syncthreads();
        #pragma unroll
        for (int k = 0; k < 8; k++) {
            float af[8], bf[8];
            *(float4*)&af[0] = *(const float4*)&As[k][ty*8];
            *(float4*)&af[4] = *(const float4*)&As[k][ty*8+4];
            *(float4*)&bf[0] = *(const float4*)&Bs[k][tx*8];
            *(float4*)&bf[4] = *(const float4*)&Bs[k][tx*8+4];
            #pragma unroll
            for (int i = 0; i < 8; i++)
                #pragma unroll
                for (int j = 0; j < 8; j++)
                    acc[i][j] += af[i] * bf[j];
        }
        __syncthreads();
    }
    #pragma unroll
    for (int i = 0; i < 8; i++) {
        int m = bm + ty*8 + i;
        float* cptr = C + (size_t)m * ldN + bn + tx*8;
        #pragma unroll
        for (int j = 0; j < 8; j += 4) {
            float4 v;
            v.x = acc[i][j+0] + bias[bn + tx*8 + j+0];
            v.y = acc[i][j+1] + bias[bn + tx*8 + j+1];
            v.z = acc[i][j+2] + bias[bn + tx*8 + j+2];
            v.w = acc[i][j+3] + bias[bn + tx*8 + j+3];
            *(float4*)(cptr + j) = v;
        }
    }
}

// ---------------- keys via mma.sync tf32 (raw fp32 fed, HW truncates) -------
// keys[6272 x 512] = features[6272 x 512] @ wk^T + bk.  grid (2, 49).
#define KPAD   36
#define K_ASZ  (128*KPAD)
#define K_BSZ  (256*KPAD)
#define K_SMEMB ((2*K_ASZ + 2*K_BSZ)*4)

__device__ __forceinline__ void hmma_tf32(float& c0, float& c1, float& c2, float& c3,
                                          uint32_t a0, uint32_t a1, uint32_t a2, uint32_t a3,
                                          uint32_t b0, uint32_t b1) {
    asm volatile("mma.sync.aligned.m16n8k8.row.col.f32.tf32.tf32.f32 "
                 "{%0,%1,%2,%3}, {%4,%5,%6,%7}, {%8,%9}, {%0,%1,%2,%3};"
                 : "+f"(c0), "+f"(c1), "+f"(c2), "+f"(c3)
                 : "r"(a0), "r"(a1), "r"(a2), "r"(a3), "r"(b0), "r"(b1));
}

__global__ void __launch_bounds__(256, 1) keys_mma(
    const float* __restrict__ A, const float* __restrict__ Bw,
    const float* __restrict__ bias, float* __restrict__ C)
{
    extern __shared__ float smf[];
    float* As = smf;
    float* Bs = smf + 2*K_ASZ;

    const int tid  = threadIdx.x;
    const int lane = tid & 31, wid = tid >> 5;
    const int wm = (wid >> 2) * 64;
    const int wn = (wid & 3)  * 64;
    const int grp = lane >> 2;
    const int tig = lane & 3;
    const int bn = blockIdx.x * 256;
    const int bm = blockIdx.y * 128;

    const float* Ab = A  + (size_t)bm * 512;
    const float* Bb = Bw + (size_t)bn * 512;

    const int lrowA = tid >> 3;
    const int lc4   = (tid & 7) * 4;

    float acc[4][8][4];
    #pragma unroll
    for (int i = 0; i < 4; i++)
        #pragma unroll
        for (int j = 0; j < 8; j++)
            #pragma unroll
            for (int k = 0; k < 4; k++) acc[i][j][k] = 0.f;

    float4 ra[4], rb[8];
    #pragma unroll
    for (int p = 0; p < 4; p++)
        ra[p] = *(const float4*)(Ab + (size_t)(p*32 + lrowA) * 512 + lc4);
    #pragma unroll
    for (int p = 0; p < 8; p++)
        rb[p] = *(const float4*)(Bb + (size_t)(p*32 + lrowA) * 512 + lc4);
    #pragma unroll
    for (int p = 0; p < 4; p++)
        *(float4*)(As + (p*32 + lrowA)*KPAD + lc4) = ra[p];
    #pragma unroll
    for (int p = 0; p < 8; p++)
        *(float4*)(Bs + (p*32 + lrowA)*KPAD + lc4) = rb[p];
    __syncthreads();

    #pragma unroll 1
    for (int kt = 0; kt < 16; kt++) {
        const int buf = kt & 1;
        const float* Asb = As + buf * K_ASZ;
        const float* Bsb = Bs + buf * K_BSZ;

        if (kt < 15) {
            const float* Aq = Ab + (kt+1)*32;
            const float* Bq = Bb + (kt+1)*32;
            #pragma unroll
            for (int p = 0; p < 4; p++)
                ra[p] = *(const float4*)(Aq + (size_t)(p*32 + lrowA) * 512 + lc4);
            #pragma unroll
            for (int p = 0; p < 8; p++)
                rb[p] = *(const float4*)(Bq + (size_t)(p*32 + lrowA) * 512 + lc4);
        }

        #pragma unroll
        for (int k8 = 0; k8 < 4; k8++) {
            const int kc = k8*8 + tig;
            uint32_t af[4][4];
            #pragma unroll
            for (int mi = 0; mi < 4; mi++) {
                const float* ar = Asb + (wm + mi*16 + grp)*KPAD;
                af[mi][0] = __float_as_uint(ar[kc]);
                af[mi][1] = __float_as_uint(ar[8*KPAD + kc]);
                af[mi][2] = __float_as_uint(ar[kc + 4]);
                af[mi][3] = __float_as_uint(ar[8*KPAD + kc + 4]);
            }
            #pragma unroll
            for (int nj = 0; nj < 8; nj++) {
                const float* br = Bsb + (wn + nj*8 + grp)*KPAD + k8*8;
                uint32_t b0 = __float_as_uint(br[tig]);
                uint32_t b1 = __float_as_uint(br[tig + 4]);
                #pragma unroll
                for (int mi = 0; mi < 4; mi++)
                    hmma_tf32(acc[mi][nj][0], acc[mi][nj][1], acc[mi][nj][2], acc[mi][nj][3],
                              af[mi][0], af[mi][1], af[mi][2], af[mi][3], b0, b1);
            }
        }

        if (kt < 15) {
            float* Asn = As + (buf ^ 1) * K_ASZ;
            float* Bsn = Bs + (buf ^ 1) * K_BSZ;
            #pragma unroll
            for (int p = 0; p < 4; p++)
                *(float4*)(Asn + (p*32 + lrowA)*KPAD + lc4) = ra[p];
            #pragma unroll
            for (int p = 0; p < 8; p++)
                *(float4*)(Bsn + (p*32 + lrowA)*KPAD + lc4) = rb[p];
        }
        __syncthreads();
    }

    #pragma unroll
    for (int mi = 0; mi < 4; mi++) {
        const int m = bm + wm + mi*16 + grp;
        #pragma unroll
        for (int nj = 0; nj < 8; nj++) {
            const int n = bn + wn + nj*8 + 2*tig;
            float bx = bias[n], by = bias[n + 1];
            *(float2*)(C + (size_t)m * 512 + n) =
                make_float2(acc[mi][nj][0] + bx, acc[mi][nj][1] + by);
            *(float2*)(C + (size_t)(m + 8) * 512 + n) =
                make_float2(acc[mi][nj][2] + bx, acc[mi][nj][3] + by);
        }
    }
}

// ---------------- fused attention (round-3 version) ----------------
__global__ void att_fused(const float* __restrict__ h3, const float* __restrict__ wq,
                          const float* __restrict__ bq, const float* __restrict__ keys,
                          const float* __restrict__ features, const float* __restrict__ v_w,
                          const float* __restrict__ v_b, const float* __restrict__ fc0_w,
                          const float* __restrict__ fc0_b, float* __restrict__ ctx_out)
{
    const int b = blockIdx.x;
    const int tid = threadIdx.x;   // 256
    __shared__ float hs_[512], qs[512], vw[512], cs[512];
    __shared__ float e[64];

    for (int i = tid; i < 512; i += 256) { hs_[i] = h3[b*512 + i]; vw[i] = v_w[i]; }
    __syncthreads();

    for (int j = tid; j < 512; j += 256) {
        const float* wr = wq + (size_t)j * 512;
        float acc = 0.f;
        #pragma unroll 8
        for (int k = 0; k < 512; k += 4) {
            float4 w = *(const float4*)(wr + k);
            acc += hs_[k]*w.x + hs_[k+1]*w.y + hs_[k+2]*w.z + hs_[k+3]*w.w;
        }
        qs[j] = acc + bq[j];
    }
    __syncthreads();

    const int warp = tid >> 5, lane = tid & 31;
    for (int s = warp; s < SEQ; s += 8) {
        const float* kp = keys + ((size_t)b * SEQ + s) * 512;
        float acc = 0.f;
        #pragma unroll
        for (int k = lane; k < 512; k += 32)
            acc += tanhf(qs[k] + kp[k]) * vw[k];
        #pragma unroll
        for (int o = 16; o; o >>= 1) acc += __shfl_xor_sync(0xffffffffu, acc, o);
        if (!lane) e[s] = acc + v_b[0];
    }
    __syncthreads();

    if (warp == 0) {
        float v1 = (lane < SEQ) ? e[lane] : -1e30f;
        float v2 = (lane + 32 < SEQ) ? e[lane + 32] : -1e30f;
        float m = fmaxf(v1, v2);
        #pragma unroll
        for (int o = 16; o; o >>= 1) m = fmaxf(m, __shfl_xor_sync(0xffffffffu, m, o));
        float e1 = (lane < SEQ) ? expf(v1 - m) : 0.f;
        float e2 = (lane + 32 < SEQ) ? expf(v2 - m) : 0.f;
        float s = e1 + e2;
        #pragma unroll
        for (int o = 16; o; o >>= 1) s += __shfl_xor_sync(0xffffffffu, s, o);
        float inv = 1.f / s;
        if (lane < SEQ) e[lane] = e1 * inv;
        if (lane + 32 < SEQ) e[lane + 32] = e2 * inv;
    }
    __syncthreads();

    for (int k = tid; k < 512; k += 256) {
        float acc = 0.f;
        const float* f = features + (size_t)b * SEQ * 512 + k;
        #pragma unroll 7
        for (int s = 0; s < SEQ; s++) acc += e[s] * f[(size_t)s * 512];
        cs[k] = acc;
    }
    __syncthreads();

    for (int j = tid; j < 512; j += 256) {
        const float* wr = fc0_w + (size_t)j * 512;
        float acc = 0.f;
        #pragma unroll 8
        for (int k = 0; k < 512; k += 4) {
            float4 w = *(const float4*)(wr + k);
            acc += cs[k]*w.x + cs[k+1]*w.y + cs[k+2]*w.z + cs[k+3]*w.w;
        }
        ctx_out[b*512 + j] = acc + fc0_b[j];
    }
}

// ---------------- GRU fused GEMM (round-3 version, fp32 SIMT) ----------------
__global__ void gru_gemm(const float* __restrict__ inA, int ldA,
                         const float* __restrict__ inB,
                         const float* __restrict__ h_old,
                         const float* __restrict__ wih,
                         const float* __restrict__ whh, int Kin)
{
    __shared__ float xs[16][36];
    __shared__ float ws[3][16][68];
    const int tid = threadIdx.x;
    const int tx = tid & 15, ty = tid >> 4;
    const int bm = blockIdx.y * 32, bn = blockIdx.x * 64;
    const int K0 = blockIdx.z * 256;
    const bool isH = (K0 >= Kin);

    const float* src; int sld; int koff;
    if (isH)            { src = h_old; sld = 512; koff = K0 - Kin; }
    else if (K0 < 512)  { src = inA;   sld = ldA; koff = K0; }
    else                { src = inB;   sld = 512; koff = K0 - 512; }
    const float* wsrc; int wld; int wkoff;
    if (isH) { wsrc = whh; wld = 512; wkoff = K0 - Kin; }
    else     { wsrc = wih; wld = Kin; wkoff = K0; }

    float aR[4][4], aZ[4][4], aN[4][4];
    #pragma unroll
    for (int i = 0; i < 4; i++)
        #pragma unroll
        for (int j = 0; j < 4; j++) { aR[i][j]=0.f; aZ[i][j]=0.f; aN[i][j]=0.f; }

    for (int kb = 0; kb < 256; kb += 16) {
        #pragma unroll
        for (int i = 0; i < 4; i++) {
            int idx = tid + i * 128;
            int kk = idx & 15, m = idx >> 4;
            xs[kk][m] = src[(size_t)(bm + m) * sld + koff + kb + kk];
        }
        #pragma unroll
        for (int i = 0; i < 24; i++) {
            int idx = tid + i * 128;
            int kk = idx & 15;
            int r  = idx >> 4;
            int n  = r & 63;
            int g  = r >> 6;
            ws[g][kk][n] = wsrc[(size_t)(g*512 + bn + n) * wld + wkoff + kb + kk];
        }
        __syncthreads();
        #pragma unroll
        for (int k = 0; k < 16; k++) {
            float4 xv = *(const float4*)&xs[k][ty*4];
            float4 wr = *(const float4*)&ws[0][k][tx*4];
            float4 wz = *(const float4*)&ws[1][k][tx*4];
            float4 wn = *(const float4*)&ws[2][k][tx*4];
            float xa[4] = {xv.x, xv.y, xv.z, xv.w};
            float ra[4] = {wr.x, wr.y, wr.z, wr.w};
            float za[4] = {wz.x, wz.y, wz.z, wz.w};
            float na[4] = {wn.x, wn.y, wn.z, wn.w};
            #pragma unroll
            for (int i = 0; i < 4; i++)
                #pragma unroll
                for (int j = 0; j < 4; j++) {
                    aR[i][j] += xa[i] * ra[j];
                    aZ[i][j] += xa[i] * za[j];
                    aN[i][j] += xa[i] * na[j];
                }
        }
        __syncthreads();
    }

    const int z = blockIdx.z;
    float* pR = g_part + (size_t)(z*3 + 0) * BH;
    float* pZ = g_part + (size_t)(z*3 + 1) * BH;
    float* pN = g_part + (size_t)(z*3 + 2) * BH;
    #pragma unroll
    for (int i = 0; i < 4; i++) {
        int off = (bm + ty*4 + i) * 512 + bn + tx*4;
        *(float4*)(pR + off) = *(float4*)&aR[i][0];
        *(float4*)(pZ + off) = *(float4*)&aZ[i][0];
        *(float4*)(pN + off) = *(float4*)&aN[i][0];
    }
}

// ---------------- gate kernel (hs out as fp16) ----------------
__global__ void gate_kernel(int nchunks, int zin,
                            const float* __restrict__ bih, const float* __restrict__ bhh,
                            const float* __restrict__ h_old, float* __restrict__ h_new,
                            __half* __restrict__ hs_out)
{
    int idx = blockIdx.x * 256 + threadIdx.x;
    int c = idx & 511;
    float r = 0.f, z = 0.f, in = 0.f, hn = 0.f;
    for (int ch = 0; ch < zin; ch++) {
        r  += g_part[(size_t)(ch*3 + 0) * BH + idx];
        z  += g_part[(size_t)(ch*3 + 1) * BH + idx];
        in += g_part[(size_t)(ch*3 + 2) * BH + idx];
    }
    for (int ch = zin; ch < nchunks; ch++) {
        r  += g_part[(size_t)(ch*3 + 0) * BH + idx];
        z  += g_part[(size_t)(ch*3 + 1) * BH + idx];
        hn += g_part[(size_t)(ch*3 + 2) * BH + idx];
    }
    r  += bih[c]        + bhh[c];
    z  += bih[512 + c]  + bhh[512 + c];
    in += bih[1024 + c];
    hn += bhh[1024 + c];
    r = 1.f / (1.f + expf(-r));
    z = 1.f / (1.f + expf(-z));
    float n = tanhf(in + r * hn);
    float h = (1.f - z) * n + z * h_old[idx];
    h_new[idx] = h;
    if (hs_out) hs_out[idx] = __float2half_rn(h);
}

// ---------------- fc2 via mma.sync fp16 (m16n8k16) ----------------
// out[b][t][:] = hs[t*128+b] @ w2h^T + fc2_b.  Tile 128x256, BK=32 halves.
#define F2_PAD  40                      // halves per smem row
#define F2_ASZ  (128*F2_PAD)            // halves per A stage
#define F2_BSZ  (256*F2_PAD)
#define F2_SMEM ((2*F2_ASZ + 2*F2_BSZ)*2)

__device__ __forceinline__ void hmma_fp16(float& c0, float& c1, float& c2, float& c3,
                                          uint32_t a0, uint32_t a1, uint32_t a2, uint32_t a3,
                                          uint32_t b0, uint32_t b1) {
    asm volatile("mma.sync.aligned.m16n8k16.row.col.f32.f16.f16.f32 "
                 "{%0,%1,%2,%3}, {%4,%5,%6,%7}, {%8,%9}, {%0,%1,%2,%3};"
                 : "+f"(c0), "+f"(c1), "+f"(c2), "+f"(c3)
                 : "r"(a0), "r"(a1), "r"(a2), "r"(a3), "r"(b0), "r"(b1));
}

__global__ void __launch_bounds__(256, 1) fc2_mma_fp16(
    const __half* __restrict__ A, const __half* __restrict__ Bw,
    const float* __restrict__ bias, float* __restrict__ out)
{
    extern __shared__ __half smh[];
    __half* As = smh;                  // [2][128][40]
    __half* Bs = smh + 2*F2_ASZ;       // [2][256][40]

    const int tid  = threadIdx.x;
    const int lane = tid & 31, wid = tid >> 5;
    const int wm = (wid >> 2) * 64;
    const int wn = (wid & 3)  * 64;
    const int grp = lane >> 2;
    const int tig = lane & 3;
    const int bn = blockIdx.x * 256;
    const int t  = blockIdx.y;

    const __half* Ab = A  + (size_t)t  * 128 * 512;
    const __half* Bb = Bw + (size_t)bn * 512;

    const int lrow = tid >> 2;          // unused base; loads use idx scheme
    (void)lrow;

    float acc[4][8][4];
    #pragma unroll
    for (int i = 0; i < 4; i++)
        #pragma unroll
        for (int j = 0; j < 8; j++)
            #pragma unroll
            for (int k = 0; k < 4; k++) acc[i][j][k] = 0.f;

    uint4 ra[2], rb[4];
    // prologue kt=0
    #pragma unroll
    for (int p = 0; p < 2; p++) {
        int idx = tid + p * 256;
        int row = idx >> 2, c8 = (idx & 3) * 8;
        ra[p] = *(const uint4*)(Ab + (size_t)row * 512 + c8);
    }
    #pragma unroll
    for (int p = 0; p < 4; p++) {
        int idx = tid + p * 256;
        int row = idx >> 2, c8 = (idx & 3) * 8;
        rb[p] = *(const uint4*)(Bb + (size_t)row * 512 + c8);
    }
    #pragma unroll
    for (int p = 0; p < 2; p++) {
        int idx = tid + p * 256;
        int row = idx >> 2, c8 = (idx & 3) * 8;
        *(uint4*)(As + row*F2_PAD + c8) = ra[p];
    }
    #pragma unroll
    for (int p = 0; p < 4; p++) {
        int idx = tid + p * 256;
        int row = idx >> 2, c8 = (idx & 3) * 8;
        *(uint4*)(Bs + row*F2_PAD + c8) = rb[p];
    }
    __syncthreads();

    #pragma unroll 1
    for (int kt = 0; kt < 16; kt++) {
        const int buf = kt & 1;
        const __half* Asb = As + buf * F2_ASZ;
        const __half* Bsb = Bs + buf * F2_BSZ;

        if (kt < 15) {
            const __half* Aq = Ab + (kt+1)*32;
            const __half* Bq = Bb + (kt+1)*32;
            #pragma unroll
            for (int p = 0; p < 2; p++) {
                int idx = tid + p * 256;
                int row = idx >> 2, c8 = (idx & 3) * 8;
                ra[p] = *(const uint4*)(Aq + (size_t)row * 512 + c8);
            }
            #pragma unroll
            for (int p = 0; p < 4; p++) {
                int idx = tid + p * 256;
                int row = idx >> 2, c8 = (idx & 3) * 8;
                rb[p] = *(const uint4*)(Bq + (size_t)row * 512 + c8);
            }
        }

        #pragma unroll
        for (int k16 = 0; k16 < 2; k16++) {
            const int kb = k16*16 + tig*2;
            uint32_t af[4][4];
            #pragma unroll
            for (int mi = 0; mi < 4; mi++) {
                const __half* ar = Asb + (wm + mi*16 + grp)*F2_PAD;
                af[mi][0] = *(const uint32_t*)(ar + kb);
                af[mi][1] = *(const uint32_t*)(ar + 8*F2_PAD + kb);
                af[mi][2] = *(const uint32_t*)(ar + kb + 8);
                af[mi][3] = *(const uint32_t*)(ar + 8*F2_PAD + kb + 8);
            }
            #pragma unroll
            for (int nj = 0; nj < 8; nj++) {
                const __half* br = Bsb + (wn + nj*8 + grp)*F2_PAD + kb;
                uint32_t b0 = *(const uint32_t*)(br);
                uint32_t b1 = *(const uint32_t*)(br + 8);
                #pragma unroll
                for (int mi = 0; mi < 4; mi++)
                    hmma_fp16(acc[mi][nj][0], acc[mi][nj][1], acc[mi][nj][2], acc[mi][nj][3],
                              af[mi][0], af[mi][1], af[mi][2], af[mi][3], b0, b1);
            }
        }

        if (kt < 15) {
            __half* Asn = As + (buf ^ 1) * F2_ASZ;
            __half* Bsn = Bs + (buf ^ 1) * F2_BSZ;
            #pragma unroll
            for (int p = 0; p < 2; p++) {
                int idx = tid + p * 256;
                int row = idx >> 2, c8 = (idx & 3) * 8;
                *(uint4*)(Asn + row*F2_PAD + c8) = ra[p];
            }
            #pragma unroll
            for (int p = 0; p < 4; p++) {
                int idx = tid + p * 256;
                int row = idx >> 2, c8 = (idx & 3) * 8;
                *(uint4*)(Bsn + row*F2_PAD + c8) = rb[p];
            }
        }
        __syncthreads();
    }

    // epilogue: bias + scatter out[b][t][n]
    #pragma unroll
    for (int mi = 0; mi < 4; mi++) {
        const int b0 = wm + mi*16 + grp;
        float* o0 = out + ((size_t)b0       * NSTEP + t) * VOCAB + bn + wn;
        float* o8 = out + ((size_t)(b0 + 8) * NSTEP + t) * VOCAB + bn + wn;
        #pragma unroll
        for (int nj = 0; nj < 8; nj++) {
            const int n = nj*8 + 2*tig;
            float bx = bias[bn + wn + n];
            float by = bias[bn + wn + n + 1];
            *(float2*)(o0 + n) = make_float2(acc[mi][nj][0] + bx, acc[mi][nj][1] + by);
            *(float2*)(o8 + n) = make_float2(acc[mi][nj][2] + bx, acc[mi][nj][3] + by);
        }
    }
}

// ---------------- host launch ----------------
extern "C" void kernel_launch(void* const* d_in, const int* in_sizes, int n_in,
                              void* d_out, int out_size)
{
    const float* features = (const float*)d_in[0];
    const int*   caps     = (const int*)  d_in[1];
    const float* emb      = (const float*)d_in[2];
    const float* fc1_w    = (const float*)d_in[3];
    const float* fc1_b    = (const float*)d_in[4];
    const float* fc0_w    = (const float*)d_in[5];
    const float* fc0_b    = (const float*)d_in[6];
    const float* wq       = (const float*)d_in[7];
    const float* bq       = (const float*)d_in[8];
    const float* wk       = (const float*)d_in[9];
    const float* bk       = (const float*)d_in[10];
    const float* v_w      = (const float*)d_in[11];
    const float* v_b      = (const float*)d_in[12];
    const float* wih0     = (const float*)d_in[13];
    const float* whh0     = (const float*)d_in[14];
    const float* bih0     = (const float*)d_in[15];
    const float* bhh0     = (const float*)d_in[16];
    const float* wihr     = (const float*)d_in[17];
    const float* whhr     = (const float*)d_in[18];
    const float* bihr     = (const float*)d_in[19];
    const float* bhhr     = (const float*)d_in[20];
    const float* fc2_w    = (const float*)d_in[21];
    const float* fc2_b    = (const float*)d_in[22];
    float* out = (float*)d_out;

    float *px, *pkeys, *pctx, *ph;
    __half *phsh, *pw2h;
    cudaGetSymbolAddress((void**)&px,    g_x);
    cudaGetSymbolAddress((void**)&pkeys, g_keys);
    cudaGetSymbolAddress((void**)&pctx,  g_ctx);
    cudaGetSymbolAddress((void**)&ph,    g_h);
    cudaGetSymbolAddress((void**)&phsh,  g_hsh);
    cudaGetSymbolAddress((void**)&pw2h,  g_w2h);

    cudaFuncSetAttribute(fc2_mma_fp16, cudaFuncAttributeMaxDynamicSharedMemorySize, F2_SMEM);
    cudaFuncSetAttribute(keys_mma,     cudaFuncAttributeMaxDynamicSharedMemorySize, K_SMEMB);

    init_kernel<<<1024, 256>>>();
    cvt_w2_kernel<<<VOCAB*HID/8/256, 256>>>(fc2_w);

    // x = emb[captions[:, :15]] @ fc1_w^T + fc1_b   (SIMT fp32, gather)
    gemm_big<1><<<dim3(4, 15), 256>>>(emb, fc1_w, fc1_b, px, 512, 512, caps);
    // keys = features @ wk^T + bk                   (tf32 MMA)
    keys_mma<<<dim3(2, 49), 256, K_SMEMB>>>(features, wk, bk, pkeys);

    for (int t = 0; t < NSTEP; t++) {
        const float* hold = ph + (t & 1) * (4 * BH);
        float*       hnew = ph + ((t & 1) ^ 1) * (4 * BH);

        att_fused<<<128, 256>>>(hold + 3 * BH, wq, bq, pkeys, features,
                                v_w, v_b, fc0_w, fc0_b, pctx);

        gru_gemm<<<dim3(8, 4, 6), 128>>>(px + t * HID, NSTEP * HID, pctx,
                                         hold, wih0, whh0, 1024);
        gate_kernel<<<256, 256>>>(6, 4, bih0, bhh0, hold, hnew, nullptr);

        for (int l = 1; l < 4; l++) {
            gru_gemm<<<dim3(8, 4, 4), 128>>>(hnew + (l - 1) * BH, HID, nullptr,
                                             hold + l * BH,
                                             wihr + (size_t)(l - 1) * 1536 * 512,
                                             whhr + (size_t)(l - 1) * 1536 * 512, 512);
            gate_kernel<<<256, 256>>>(4, 2,
                                      bihr + (l - 1) * 1536, bhhr + (l - 1) * 1536,
                                      hold + l * BH, hnew + l * BH,
                                      (l == 3) ? (phsh + t * BH) : nullptr);
        }
    }

    fc2_mma_fp16<<<dim3(VOCAB/256, NSTEP), 256, F2_SMEM>>>(phsh, pw2h, fc2_b, out);
}

// round 6
// speedup vs baseline: 1.2787x; 1.0666x over previous
#include <cuda_runtime.h>
#include <cuda_fp16.h>
#include <math.h>
#include <cstdint>

#define BATCH 128
#define SEQ   49
#define HID   512
#define VOCAB 32000
#define NSTEP 15
#define BH    (BATCH*HID)

// ---------------- device scratch ----------------
__device__ float  g_x[BATCH*NSTEP*HID];
__device__ float  g_keys[BATCH*SEQ*HID];
__device__ float  g_ctx[BH];
__device__ float  g_h[2*4*BH];
__device__ __half g_hsh[NSTEP*BH];          // fp16 top-layer h (fc2 A operand)
__device__ float  g_part[6*3*BH];
__device__ __half g_w2h[VOCAB*HID];         // fp16 fc2 weights
#define WG_TOT (1536*1536 + 3*1536*1024)
__device__ __half g_wh[WG_TOT];             // GRU packed [wih|whh] fp16 hi
__device__ __half g_wl[WG_TOT];             // fp16 lo
__device__ int    g_cnt[8];

// ---------------- init ----------------
__global__ void init_kernel() {
    int idx = blockIdx.x * 256 + threadIdx.x;
    if (idx < 4*BH) g_h[idx] = 0.f;
    if (blockIdx.x == 0 && threadIdx.x < 8) g_cnt[threadIdx.x] = 0;
}

// ---------------- fc2 weights -> fp16 ----------------
__global__ void cvt_w2_kernel(const float* __restrict__ w) {
    int i = blockIdx.x * 256 + threadIdx.x;
    const float4* in = (const float4*)w;
    float4 v0 = in[2*i], v1 = in[2*i + 1];
    __half2 h0 = __floats2half2_rn(v0.x, v0.y);
    __half2 h1 = __floats2half2_rn(v0.z, v0.w);
    __half2 h2 = __floats2half2_rn(v1.x, v1.y);
    __half2 h3 = __floats2half2_rn(v1.z, v1.w);
    uint4 o;
    o.x = *(uint32_t*)&h0; o.y = *(uint32_t*)&h1;
    o.z = *(uint32_t*)&h2; o.w = *(uint32_t*)&h3;
    ((uint4*)g_w2h)[i] = o;
}

// ---------------- GRU weights -> packed fp16 hi/lo ----------------
__global__ void wsplit_gru(__half* __restrict__ dh, __half* __restrict__ dl,
                           const float* __restrict__ wih, const float* __restrict__ whh,
                           int Kin, int Ktot) {
    int i = blockIdx.x * 256 + threadIdx.x;          // 8-element chunks
    int k8 = Ktot >> 3;
    int row = i / k8;
    if (row >= 1536) return;
    int c = (i - row * k8) * 8;
    const float* sp = (c < Kin) ? (wih + (size_t)row * Kin + c)
                                : (whh + (size_t)row * 512 + (c - Kin));
    uint32_t hi[4], lo[4];
    #pragma unroll
    for (int j = 0; j < 4; j++) {
        float a = sp[2*j], b = sp[2*j + 1];
        __half2 h2 = __floats2half2_rn(a, b);
        float2 bb = __half22float2(h2);
        __half2 l2 = __floats2half2_rn(a - bb.x, b - bb.y);
        hi[j] = *(uint32_t*)&h2; lo[j] = *(uint32_t*)&l2;
    }
    *(uint4*)(dh + (size_t)row * Ktot + c) = make_uint4(hi[0], hi[1], hi[2], hi[3]);
    *(uint4*)(dl + (size_t)row * Ktot + c) = make_uint4(lo[0], lo[1], lo[2], lo[3]);
}

// ---------------- big SIMT GEMM (x precompute, fp32 exact) ----------------
template<int AMODE>
__global__ void gemm_big(const float* __restrict__ A, const float* __restrict__ W,
                         const float* __restrict__ bias, float* __restrict__ C,
                         int ldN, int Kd, const int* __restrict__ caps)
{
    __shared__ float As[8][132];
    __shared__ float Bs[8][132];
    const int tid = threadIdx.x;
    const int bm = blockIdx.y * 128;
    const int bn = blockIdx.x * 128;
    const int tx = tid & 15, ty = tid >> 4;
    const int arow = tid >> 1;
    const int acol = (tid & 1) * 4;

    const float* a_row_ptr;
    if (AMODE == 1) {
        int m = bm + arow;
        int bb = m / NSTEP, tt = m - bb * NSTEP;
        a_row_ptr = A + (size_t)caps[bb * 16 + tt] * Kd;
    } else {
        a_row_ptr = A + (size_t)(bm + arow) * Kd;
    }
    const float* w_row_ptr = W + (size_t)(bn + arow) * Kd;

    float acc[8][8];
    #pragma unroll
    for (int i = 0; i < 8; i++)
        #pragma unroll
        for (int j = 0; j < 8; j++) acc[i][j] = 0.f;

    for (int k0 = 0; k0 < Kd; k0 += 8) {
        float4 av = *(const float4*)(a_row_ptr + k0 + acol);
        float4 wv = *(const float4*)(w_row_ptr + k0 + acol);
        As[acol+0][arow] = av.x; As[acol+1][arow] = av.y;
        As[acol+2][arow] = av.z; As[acol+3][arow] = av.w;
        Bs[acol+0][arow] = wv.x; Bs[acol+1][arow] = wv.y;
        Bs[acol+2][arow] = wv.z; Bs[acol+3][arow] = wv.w;
        __syncthreads();
        #pragma unroll
        for (int k = 0; k < 8; k++) {
            float af[8], bf[8];
            *(float4*)&af[0] = *(const float4*)&As[k][ty*8];
            *(float4*)&af[4] = *(const float4*)&As[k][ty*8+4];
            *(float4*)&bf[0] = *(const float4*)&Bs[k][tx*8];
            *(float4*)&bf[4] = *(const float4*)&Bs[k][tx*8+4];
            #pragma unroll
            for (int i = 0; i < 8; i++)
                #pragma unroll
                for (int j = 0; j < 8; j++)
                    acc[i][j] += af[i] * bf[j];
        }
        __syncthreads();
    }
    #pragma unroll
    for (int i = 0; i < 8; i++) {
        int m = bm + ty*8 + i;
        float* cptr = C + (size_t)m * ldN + bn + tx*8;
        #pragma unroll
        for (int j = 0; j < 8; j += 4) {
            float4 v;
            v.x = acc[i][j+0] + bias[bn + tx*8 + j+0];
            v.y = acc[i][j+1] + bias[bn + tx*8 + j+1];
            v.z = acc[i][j+2] + bias[bn + tx*8 + j+2];
            v.w = acc[i][j+3] + bias[bn + tx*8 + j+3];
            *(float4*)(cptr + j) = v;
        }
    }
}

// ---------------- keys via mma.sync tf32 ----------------
#define KPAD   36
#define K_ASZ  (128*KPAD)
#define K_BSZ  (256*KPAD)
#define K_SMEMB ((2*K_ASZ + 2*K_BSZ)*4)

__device__ __forceinline__ void hmma_tf32(float& c0, float& c1, float& c2, float& c3,
                                          uint32_t a0, uint32_t a1, uint32_t a2, uint32_t a3,
                                          uint32_t b0, uint32_t b1) {
    asm volatile("mma.sync.aligned.m16n8k8.row.col.f32.tf32.tf32.f32 "
                 "{%0,%1,%2,%3}, {%4,%5,%6,%7}, {%8,%9}, {%0,%1,%2,%3};"
                 : "+f"(c0), "+f"(c1), "+f"(c2), "+f"(c3)
                 : "r"(a0), "r"(a1), "r"(a2), "r"(a3), "r"(b0), "r"(b1));
}

__global__ void __launch_bounds__(256, 1) keys_mma(
    const float* __restrict__ A, const float* __restrict__ Bw,
    const float* __restrict__ bias, float* __restrict__ C)
{
    extern __shared__ float smf[];
    float* As = smf;
    float* Bs = smf + 2*K_ASZ;

    const int tid  = threadIdx.x;
    const int lane = tid & 31, wid = tid >> 5;
    const int wm = (wid >> 2) * 64;
    const int wn = (wid & 3)  * 64;
    const int grp = lane >> 2;
    const int tig = lane & 3;
    const int bn = blockIdx.x * 256;
    const int bm = blockIdx.y * 128;

    const float* Ab = A  + (size_t)bm * 512;
    const float* Bb = Bw + (size_t)bn * 512;

    const int lrowA = tid >> 3;
    const int lc4   = (tid & 7) * 4;

    float acc[4][8][4];
    #pragma unroll
    for (int i = 0; i < 4; i++)
        #pragma unroll
        for (int j = 0; j < 8; j++)
            #pragma unroll
            for (int k = 0; k < 4; k++) acc[i][j][k] = 0.f;

    float4 ra[4], rb[8];
    #pragma unroll
    for (int p = 0; p < 4; p++)
        ra[p] = *(const float4*)(Ab + (size_t)(p*32 + lrowA) * 512 + lc4);
    #pragma unroll
    for (int p = 0; p < 8; p++)
        rb[p] = *(const float4*)(Bb + (size_t)(p*32 + lrowA) * 512 + lc4);
    #pragma unroll
    for (int p = 0; p < 4; p++)
        *(float4*)(As + (p*32 + lrowA)*KPAD + lc4) = ra[p];
    #pragma unroll
    for (int p = 0; p < 8; p++)
        *(float4*)(Bs + (p*32 + lrowA)*KPAD + lc4) = rb[p];
    __syncthreads();

    #pragma unroll 1
    for (int kt = 0; kt < 16; kt++) {
        const int buf = kt & 1;
        const float* Asb = As + buf * K_ASZ;
        const float* Bsb = Bs + buf * K_BSZ;

        if (kt < 15) {
            const float* Aq = Ab + (kt+1)*32;
            const float* Bq = Bb + (kt+1)*32;
            #pragma unroll
            for (int p = 0; p < 4; p++)
                ra[p] = *(const float4*)(Aq + (size_t)(p*32 + lrowA) * 512 + lc4);
            #pragma unroll
            for (int p = 0; p < 8; p++)
                rb[p] = *(const float4*)(Bq + (size_t)(p*32 + lrowA) * 512 + lc4);
        }

        #pragma unroll
        for (int k8 = 0; k8 < 4; k8++) {
            const int kc = k8*8 + tig;
            uint32_t af[4][4];
            #pragma unroll
            for (int mi = 0; mi < 4; mi++) {
                const float* ar = Asb + (wm + mi*16 + grp)*KPAD;
                af[mi][0] = __float_as_uint(ar[kc]);
                af[mi][1] = __float_as_uint(ar[8*KPAD + kc]);
                af[mi][2] = __float_as_uint(ar[kc + 4]);
                af[mi][3] = __float_as_uint(ar[8*KPAD + kc + 4]);
            }
            #pragma unroll
            for (int nj = 0; nj < 8; nj++) {
                const float* br = Bsb + (wn + nj*8 + grp)*KPAD + k8*8;
                uint32_t b0 = __float_as_uint(br[tig]);
                uint32_t b1 = __float_as_uint(br[tig + 4]);
                #pragma unroll
                for (int mi = 0; mi < 4; mi++)
                    hmma_tf32(acc[mi][nj][0], acc[mi][nj][1], acc[mi][nj][2], acc[mi][nj][3],
                              af[mi][0], af[mi][1], af[mi][2], af[mi][3], b0, b1);
            }
        }

        if (kt < 15) {
            float* Asn = As + (buf ^ 1) * K_ASZ;
            float* Bsn = Bs + (buf ^ 1) * K_BSZ;
            #pragma unroll
            for (int p = 0; p < 4; p++)
                *(float4*)(Asn + (p*32 + lrowA)*KPAD + lc4) = ra[p];
            #pragma unroll
            for (int p = 0; p < 8; p++)
                *(float4*)(Bsn + (p*32 + lrowA)*KPAD + lc4) = rb[p];
        }
        __syncthreads();
    }

    #pragma unroll
    for (int mi = 0; mi < 4; mi++) {
        const int m = bm + wm + mi*16 + grp;
        #pragma unroll
        for (int nj = 0; nj < 8; nj++) {
            const int n = bn + wn + nj*8 + 2*tig;
            float bx = bias[n], by = bias[n + 1];
            *(float2*)(C + (size_t)m * 512 + n) =
                make_float2(acc[mi][nj][0] + bx, acc[mi][nj][1] + by);
            *(float2*)(C + (size_t)(m + 8) * 512 + n) =
                make_float2(acc[mi][nj][2] + bx, acc[mi][nj][3] + by);
        }
    }
}

// ---------------- fused attention ----------------
__global__ void att_fused(const float* __restrict__ h3, const float* __restrict__ wq,
                          const float* __restrict__ bq, const float* __restrict__ keys,
                          const float* __restrict__ features, const float* __restrict__ v_w,
                          const float* __restrict__ v_b, const float* __restrict__ fc0_w,
                          const float* __restrict__ fc0_b, float* __restrict__ ctx_out)
{
    const int b = blockIdx.x;
    const int tid = threadIdx.x;   // 256
    __shared__ float hs_[512], qs[512], vw[512], cs[512];
    __shared__ float e[64];

    for (int i = tid; i < 512; i += 256) { hs_[i] = h3[b*512 + i]; vw[i] = v_w[i]; }
    __syncthreads();

    for (int j = tid; j < 512; j += 256) {
        const float* wr = wq + (size_t)j * 512;
        float acc = 0.f;
        #pragma unroll 8
        for (int k = 0; k < 512; k += 4) {
            float4 w = *(const float4*)(wr + k);
            acc += hs_[k]*w.x + hs_[k+1]*w.y + hs_[k+2]*w.z + hs_[k+3]*w.w;
        }
        qs[j] = acc + bq[j];
    }
    __syncthreads();

    const int warp = tid >> 5, lane = tid & 31;
    for (int s = warp; s < SEQ; s += 8) {
        const float* kp = keys + ((size_t)b * SEQ + s) * 512;
        float acc = 0.f;
        #pragma unroll
        for (int k = lane; k < 512; k += 32)
            acc += tanhf(qs[k] + kp[k]) * vw[k];
        #pragma unroll
        for (int o = 16; o; o >>= 1) acc += __shfl_xor_sync(0xffffffffu, acc, o);
        if (!lane) e[s] = acc + v_b[0];
    }
    __syncthreads();

    if (warp == 0) {
        float v1 = (lane < SEQ) ? e[lane] : -1e30f;
        float v2 = (lane + 32 < SEQ) ? e[lane + 32] : -1e30f;
        float m = fmaxf(v1, v2);
        #pragma unroll
        for (int o = 16; o; o >>= 1) m = fmaxf(m, __shfl_xor_sync(0xffffffffu, m, o));
        float e1 = (lane < SEQ) ? expf(v1 - m) : 0.f;
        float e2 = (lane + 32 < SEQ) ? expf(v2 - m) : 0.f;
        float s = e1 + e2;
        #pragma unroll
        for (int o = 16; o; o >>= 1) s += __shfl_xor_sync(0xffffffffu, s, o);
        float inv = 1.f / s;
        if (lane < SEQ) e[lane] = e1 * inv;
        if (lane + 32 < SEQ) e[lane + 32] = e2 * inv;
    }
    __syncthreads();

    for (int k = tid; k < 512; k += 256) {
        float acc = 0.f;
        const float* f = features + (size_t)b * SEQ * 512 + k;
        #pragma unroll 7
        for (int s = 0; s < SEQ; s++) acc += e[s] * f[(size_t)s * 512];
        cs[k] = acc;
    }
    __syncthreads();

    for (int j = tid; j < 512; j += 256) {
        const float* wr = fc0_w + (size_t)j * 512;
        float acc = 0.f;
        #pragma unroll 8
        for (int k = 0; k < 512; k += 4) {
            float4 w = *(const float4*)(wr + k);
            acc += cs[k]*w.x + cs[k+1]*w.y + cs[k+2]*w.z + cs[k+3]*w.w;
        }
        ctx_out[b*512 + j] = acc + fc0_b[j];
    }
}

// =====================================================================
// GRU layer via fp16 compensated mma.sync (3 terms), gates fused.
// grid (24 n-tiles of 64 over 1536, NK k-chunks of 256), 256 threads.
// K layout: chunk pairs -> srcA (0,1), srcB (2,3), srcC (4,5); h = last 2.
// =====================================================================
#define GR_SMEM ((2*5120*2 + 2*2560*2)*2)   // halves -> bytes: 61440

__device__ __forceinline__ void hmma_fp16(float& c0, float& c1, float& c2, float& c3,
                                          uint32_t a0, uint32_t a1, uint32_t a2, uint32_t a3,
                                          uint32_t b0, uint32_t b1) {
    asm volatile("mma.sync.aligned.m16n8k16.row.col.f32.f16.f16.f32 "
                 "{%0,%1,%2,%3}, {%4,%5,%6,%7}, {%8,%9}, {%0,%1,%2,%3};"
                 : "+f"(c0), "+f"(c1), "+f"(c2), "+f"(c3)
                 : "r"(a0), "r"(a1), "r"(a2), "r"(a3), "r"(b0), "r"(b1));
}

template<int NK>
__global__ void __launch_bounds__(256, 1) gru_fp16(
    const float* __restrict__ srcA, int ldA,
    const float* __restrict__ srcB, const float* __restrict__ srcC,
    const __half* __restrict__ Wh, const __half* __restrict__ Wl, int ldK,
    const float* __restrict__ bih, const float* __restrict__ bhh,
    const float* __restrict__ h_old, float* __restrict__ h_new,
    __half* __restrict__ hs_out)
{
    extern __shared__ __half smg[];
    __half* AHI = smg;                 // [2][128*40]
    __half* ALO = AHI + 2*5120;
    __half* BHI = ALO + 2*5120;        // [2][64*40]
    __half* BLO = BHI + 2*2560;

    const int tid = threadIdx.x;
    const int lane = tid & 31, wid = tid >> 5;
    const int wm = (wid & 1) * 64;
    const int wn = (wid >> 1) * 16;
    const int grp = lane >> 2, tig = lane & 3;
    const int nt = blockIdx.x;
    const int kc = blockIdx.y;
    const int bn = nt * 64;

    const float* src; int ld;
    {
        int sel = kc >> 1;
        if (sel == 0)      { src = srcA; ld = ldA; }
        else if (sel == 1) { src = srcB; ld = 512; }
        else               { src = srcC; ld = 512; }
    }
    const int koff = (kc & 1) * 256;

    const int arow = tid >> 1;
    const int acol = (tid & 1) * 16;
    const int brow = tid >> 2;
    const int bcol = (tid & 3) * 8;

    const float*  Arow  = src + (size_t)arow * ld + koff + acol;
    const __half* Wrowh = Wh + (size_t)(bn + brow) * ldK + kc*256 + bcol;
    const __half* Wrowl = Wl + (size_t)(bn + brow) * ldK + kc*256 + bcol;

    float acc[4][2][4];
    #pragma unroll
    for (int i = 0; i < 4; i++)
        #pragma unroll
        for (int j = 0; j < 2; j++)
            #pragma unroll
            for (int k = 0; k < 4; k++) acc[i][j][k] = 0.f;

    float fa[16];
    uint4 wh4, wl4;

    // prologue: stage 0 regs
    #pragma unroll
    for (int p = 0; p < 4; p++)
        *(float4*)&fa[p*4] = *(const float4*)(Arow + p*4);
    wh4 = *(const uint4*)(Wrowh);
    wl4 = *(const uint4*)(Wrowl);

    // store stage 0
    {
        uint32_t hi[8], lo[8];
        #pragma unroll
        for (int j = 0; j < 8; j++) {
            __half2 h2 = __floats2half2_rn(fa[2*j], fa[2*j+1]);
            float2 bb = __half22float2(h2);
            __half2 l2 = __floats2half2_rn(fa[2*j] - bb.x, fa[2*j+1] - bb.y);
            hi[j] = *(uint32_t*)&h2; lo[j] = *(uint32_t*)&l2;
        }
        __half* ah = AHI + arow*40 + acol;
        __half* al = ALO + arow*40 + acol;
        *(uint4*)ah       = make_uint4(hi[0], hi[1], hi[2], hi[3]);
        *(uint4*)(ah + 8) = make_uint4(hi[4], hi[5], hi[6], hi[7]);
        *(uint4*)al       = make_uint4(lo[0], lo[1], lo[2], lo[3]);
        *(uint4*)(al + 8) = make_uint4(lo[4], lo[5], lo[6], lo[7]);
        *(uint4*)(BHI + brow*40 + bcol) = wh4;
        *(uint4*)(BLO + brow*40 + bcol) = wl4;
    }
    __syncthreads();

    #pragma unroll 1
    for (int kt = 0; kt < 8; kt++) {
        const int buf = kt & 1;
        const __half* Ah = AHI + buf*5120;
        const __half* Al = ALO + buf*5120;
        const __half* Bh = BHI + buf*2560;
        const __half* Bl = BLO + buf*2560;

        if (kt < 7) {
            #pragma unroll
            for (int p = 0; p < 4; p++)
                *(float4*)&fa[p*4] = *(const float4*)(Arow + (kt+1)*32 + p*4);
            wh4 = *(const uint4*)(Wrowh + (kt+1)*32);
            wl4 = *(const uint4*)(Wrowl + (kt+1)*32);
        }

        #pragma unroll
        for (int k16 = 0; k16 < 2; k16++) {
            const int kb = k16*16 + tig*2;
            uint32_t ah[4][4], al[4][4];
            #pragma unroll
            for (int mi = 0; mi < 4; mi++) {
                const __half* arh = Ah + (wm + mi*16 + grp)*40;
                const __half* arl = Al + (wm + mi*16 + grp)*40;
                ah[mi][0] = *(const uint32_t*)(arh + kb);
                ah[mi][1] = *(const uint32_t*)(arh + 8*40 + kb);
                ah[mi][2] = *(const uint32_t*)(arh + kb + 8);
                ah[mi][3] = *(const uint32_t*)(arh + 8*40 + kb + 8);
                al[mi][0] = *(const uint32_t*)(arl + kb);
                al[mi][1] = *(const uint32_t*)(arl + 8*40 + kb);
                al[mi][2] = *(const uint32_t*)(arl + kb + 8);
                al[mi][3] = *(const uint32_t*)(arl + 8*40 + kb + 8);
            }
            #pragma unroll
            for (int nj = 0; nj < 2; nj++) {
                const __half* brh = Bh + (wn + nj*8 + grp)*40 + kb;
                const __half* brl = Bl + (wn + nj*8 + grp)*40 + kb;
                uint32_t b0h = *(const uint32_t*)(brh);
                uint32_t b1h = *(const uint32_t*)(brh + 8);
                uint32_t b0l = *(const uint32_t*)(brl);
                uint32_t b1l = *(const uint32_t*)(brl + 8);
                #pragma unroll
                for (int mi = 0; mi < 4; mi++) {
                    hmma_fp16(acc[mi][nj][0], acc[mi][nj][1], acc[mi][nj][2], acc[mi][nj][3],
                              ah[mi][0], ah[mi][1], ah[mi][2], ah[mi][3], b0h, b1h);
                    hmma_fp16(acc[mi][nj][0], acc[mi][nj][1], acc[mi][nj][2], acc[mi][nj][3],
                              ah[mi][0], ah[mi][1], ah[mi][2], ah[mi][3], b0l, b1l);
                    hmma_fp16(acc[mi][nj][0], acc[mi][nj][1], acc[mi][nj][2], acc[mi][nj][3],
                              al[mi][0], al[mi][1], al[mi][2], al[mi][3], b0h, b1h);
                }
            }
        }

        if (kt < 7) {
            const int nb = buf ^ 1;
            uint32_t hi[8], lo[8];
            #pragma unroll
            for (int j = 0; j < 8; j++) {
                __half2 h2 = __floats2half2_rn(fa[2*j], fa[2*j+1]);
                float2 bb = __half22float2(h2);
                __half2 l2 = __floats2half2_rn(fa[2*j] - bb.x, fa[2*j+1] - bb.y);
                hi[j] = *(uint32_t*)&h2; lo[j] = *(uint32_t*)&l2;
            }
            __half* ah = AHI + nb*5120 + arow*40 + acol;
            __half* al = ALO + nb*5120 + arow*40 + acol;
            *(uint4*)ah       = make_uint4(hi[0], hi[1], hi[2], hi[3]);
            *(uint4*)(ah + 8) = make_uint4(hi[4], hi[5], hi[6], hi[7]);
            *(uint4*)al       = make_uint4(lo[0], lo[1], lo[2], lo[3]);
            *(uint4*)(al + 8) = make_uint4(lo[4], lo[5], lo[6], lo[7]);
            *(uint4*)(BHI + nb*2560 + brow*40 + bcol) = wh4;
            *(uint4*)(BLO + nb*2560 + brow*40 + bcol) = wl4;
        }
        __syncthreads();
    }

    // write partial tile: g_part[(kc*24 + nt)*8192 + m*64 + nc]
    {
        float* P = g_part + ((size_t)(kc*24 + nt)) * 8192;
        #pragma unroll
        for (int mi = 0; mi < 4; mi++) {
            #pragma unroll
            for (int nj = 0; nj < 2; nj++) {
                int m = wm + mi*16 + grp;
                int nc = wn + nj*8 + tig*2;
                *(float2*)(P + m*64 + nc)     = make_float2(acc[mi][nj][0], acc[mi][nj][1]);
                *(float2*)(P + (m+8)*64 + nc) = make_float2(acc[mi][nj][2], acc[mi][nj][3]);
            }
        }
    }

    __threadfence();
    __shared__ int sdone;
    if (tid == 0) {
        int g = nt & 7;
        int v = atomicAdd(&g_cnt[g], 1);
        int done = (v == 3*NK - 1);
        if (done) g_cnt[g] = 0;
        sdone = done;
    }
    __syncthreads();
    if (!sdone) return;
    __threadfence();

    // ---- gate epilogue (finisher block) ----
    const int g = nt & 7;
    const int cc = (tid & 15) * 4;
    const int c  = g*64 + cc;
    float4 bir = *(const float4*)(bih + c);
    float4 biz = *(const float4*)(bih + 512 + c);
    float4 bin = *(const float4*)(bih + 1024 + c);
    float4 bhr = *(const float4*)(bhh + c);
    float4 bhz = *(const float4*)(bhh + 512 + c);
    float4 bhn = *(const float4*)(bhh + 1024 + c);

    #pragma unroll
    for (int i = 0; i < 8; i++) {
        const int m = (tid >> 4) * 8 + i;
        float4 r4 = make_float4(0,0,0,0), z4 = r4, in4 = r4, hn4 = r4;
        #pragma unroll
        for (int kx = 0; kx < NK; kx++) {
            const float* Pr = g_part + ((size_t)(kx*24 + g))      * 8192 + m*64 + cc;
            const float* Pz = g_part + ((size_t)(kx*24 + 8 + g))  * 8192 + m*64 + cc;
            const float* Pn = g_part + ((size_t)(kx*24 + 16 + g)) * 8192 + m*64 + cc;
            float4 a = *(const float4*)Pr; r4.x += a.x; r4.y += a.y; r4.z += a.z; r4.w += a.w;
            a = *(const float4*)Pz;        z4.x += a.x; z4.y += a.y; z4.z += a.z; z4.w += a.w;
            a = *(const float4*)Pn;
            if (kx < NK-2) { in4.x += a.x; in4.y += a.y; in4.z += a.z; in4.w += a.w; }
            else           { hn4.x += a.x; hn4.y += a.y; hn4.z += a.z; hn4.w += a.w; }
        }
        float4 ho = *(const float4*)(h_old + (size_t)m*512 + c);
        float hv[4];
        #pragma unroll
        for (int q = 0; q < 4; q++) {
            float rp = ((float*)&r4)[q] + ((float*)&bir)[q] + ((float*)&bhr)[q];
            float zp = ((float*)&z4)[q] + ((float*)&biz)[q] + ((float*)&bhz)[q];
            float ip = ((float*)&in4)[q] + ((float*)&bin)[q];
            float hp = ((float*)&hn4)[q] + ((float*)&bhn)[q];
            float r = 1.f / (1.f + expf(-rp));
            float z = 1.f / (1.f + expf(-zp));
            float n = tanhf(ip + r * hp);
            hv[q] = (1.f - z) * n + z * ((float*)&ho)[q];
        }
        *(float4*)(h_new + (size_t)m*512 + c) = make_float4(hv[0], hv[1], hv[2], hv[3]);
        if (hs_out) {
            __half2 o0 = __floats2half2_rn(hv[0], hv[1]);
            __half2 o1 = __floats2half2_rn(hv[2], hv[3]);
            uint2 ov; ov.x = *(uint32_t*)&o0; ov.y = *(uint32_t*)&o1;
            *(uint2*)(hs_out + (size_t)m*512 + c) = ov;
        }
    }
}

// ---------------- fc2 via mma.sync fp16 (m16n8k16) ----------------
#define F2_PAD  40
#define F2_ASZ  (128*F2_PAD)
#define F2_BSZ  (256*F2_PAD)
#define F2_SMEM ((2*F2_ASZ + 2*F2_BSZ)*2)

__global__ void __launch_bounds__(256, 1) fc2_mma_fp16(
    const __half* __restrict__ A, const __half* __restrict__ Bw,
    const float* __restrict__ bias, float* __restrict__ out)
{
    extern __shared__ __half smh[];
    __half* As = smh;
    __half* Bs = smh + 2*F2_ASZ;

    const int tid  = threadIdx.x;
    const int lane = tid & 31, wid = tid >> 5;
    const int wm = (wid >> 2) * 64;
    const int wn = (wid & 3)  * 64;
    const int grp = lane >> 2;
    const int tig = lane & 3;
    const int bn = blockIdx.x * 256;
    const int t  = blockIdx.y;

    const __half* Ab = A  + (size_t)t  * 128 * 512;
    const __half* Bb = Bw + (size_t)bn * 512;

    float acc[4][8][4];
    #pragma unroll
    for (int i = 0; i < 4; i++)
        #pragma unroll
        for (int j = 0; j < 8; j++)
            #pragma unroll
            for (int k = 0; k < 4; k++) acc[i][j][k] = 0.f;

    uint4 ra[2], rb[4];
    #pragma unroll
    for (int p = 0; p < 2; p++) {
        int idx = tid + p * 256;
        int row = idx >> 2, c8 = (idx & 3) * 8;
        ra[p] = *(const uint4*)(Ab + (size_t)row * 512 + c8);
    }
    #pragma unroll
    for (int p = 0; p < 4; p++) {
        int idx = tid + p * 256;
        int row = idx >> 2, c8 = (idx & 3) * 8;
        rb[p] = *(const uint4*)(Bb + (size_t)row * 512 + c8);
    }
    #pragma unroll
    for (int p = 0; p < 2; p++) {
        int idx = tid + p * 256;
        int row = idx >> 2, c8 = (idx & 3) * 8;
        *(uint4*)(As + row*F2_PAD + c8) = ra[p];
    }
    #pragma unroll
    for (int p = 0; p < 4; p++) {
        int idx = tid + p * 256;
        int row = idx >> 2, c8 = (idx & 3) * 8;
        *(uint4*)(Bs + row*F2_PAD + c8) = rb[p];
    }
    __syncthreads();

    #pragma unroll 1
    for (int kt = 0; kt < 16; kt++) {
        const int buf = kt & 1;
        const __half* Asb = As + buf * F2_ASZ;
        const __half* Bsb = Bs + buf * F2_BSZ;

        if (kt < 15) {
            const __half* Aq = Ab + (kt+1)*32;
            const __half* Bq = Bb + (kt+1)*32;
            #pragma unroll
            for (int p = 0; p < 2; p++) {
                int idx = tid + p * 256;
                int row = idx >> 2, c8 = (idx & 3) * 8;
                ra[p] = *(const uint4*)(Aq + (size_t)row * 512 + c8);
            }
            #pragma unroll
            for (int p = 0; p < 4; p++) {
                int idx = tid + p * 256;
                int row = idx >> 2, c8 = (idx & 3) * 8;
                rb[p] = *(const uint4*)(Bq + (size_t)row * 512 + c8);
            }
        }

        #pragma unroll
        for (int k16 = 0; k16 < 2; k16++) {
            const int kb = k16*16 + tig*2;
            uint32_t af[4][4];
            #pragma unroll
            for (int mi = 0; mi < 4; mi++) {
                const __half* ar = Asb + (wm + mi*16 + grp)*F2_PAD;
                af[mi][0] = *(const uint32_t*)(ar + kb);
                af[mi][1] = *(const uint32_t*)(ar + 8*F2_PAD + kb);
                af[mi][2] = *(const uint32_t*)(ar + kb + 8);
                af[mi][3] = *(const uint32_t*)(ar + 8*F2_PAD + kb + 8);
            }
            #pragma unroll
            for (int nj = 0; nj < 8; nj++) {
                const __half* br = Bsb + (wn + nj*8 + grp)*F2_PAD + kb;
                uint32_t b0 = *(const uint32_t*)(br);
                uint32_t b1 = *(const uint32_t*)(br + 8);
                #pragma unroll
                for (int mi = 0; mi < 4; mi++)
                    hmma_fp16(acc[mi][nj][0], acc[mi][nj][1], acc[mi][nj][2], acc[mi][nj][3],
                              af[mi][0], af[mi][1], af[mi][2], af[mi][3], b0, b1);
            }
        }

        if (kt < 15) {
            __half* Asn = As + (buf ^ 1) * F2_ASZ;
            __half* Bsn = Bs + (buf ^ 1) * F2_BSZ;
            #pragma unroll
            for (int p = 0; p < 2; p++) {
                int idx = tid + p * 256;
                int row = idx >> 2, c8 = (idx & 3) * 8;
                *(uint4*)(Asn + row*F2_PAD + c8) = ra[p];
            }
            #pragma unroll
            for (int p = 0; p < 4; p++) {
                int idx = tid + p * 256;
                int row = idx >> 2, c8 = (idx & 3) * 8;
                *(uint4*)(Bsn + row*F2_PAD + c8) = rb[p];
            }
        }
        __syncthreads();
    }

    #pragma unroll
    for (int mi = 0; mi < 4; mi++) {
        const int b0 = wm + mi*16 + grp;
        float* o0 = out + ((size_t)b0       * NSTEP + t) * VOCAB + bn + wn;
        float* o8 = out + ((size_t)(b0 + 8) * NSTEP + t) * VOCAB + bn + wn;
        #pragma unroll
        for (int nj = 0; nj < 8; nj++) {
            const int n = nj*8 + 2*tig;
            float bx = bias[bn + wn + n];
            float by = bias[bn + wn + n + 1];
            *(float2*)(o0 + n) = make_float2(acc[mi][nj][0] + bx, acc[mi][nj][1] + by);
            *(float2*)(o8 + n) = make_float2(acc[mi][nj][2] + bx, acc[mi][nj][3] + by);
        }
    }
}

// ---------------- host launch ----------------
extern "C" void kernel_launch(void* const* d_in, const int* in_sizes, int n_in,
                              void* d_out, int out_size)
{
    const float* features = (const float*)d_in[0];
    const int*   caps     = (const int*)  d_in[1];
    const float* emb      = (const float*)d_in[2];
    const float* fc1_w    = (const float*)d_in[3];
    const float* fc1_b    = (const float*)d_in[4];
    const float* fc0_w    = (const float*)d_in[5];
    const float* fc0_b    = (const float*)d_in[6];
    const float* wq       = (const float*)d_in[7];
    const float* bq       = (const float*)d_in[8];
    const float* wk       = (const float*)d_in[9];
    const float* bk       = (const float*)d_in[10];
    const float* v_w      = (const float*)d_in[11];
    const float* v_b      = (const float*)d_in[12];
    const float* wih0     = (const float*)d_in[13];
    const float* whh0     = (const float*)d_in[14];
    const float* bih0     = (const float*)d_in[15];
    const float* bhh0     = (const float*)d_in[16];
    const float* wihr     = (const float*)d_in[17];
    const float* whhr     = (const float*)d_in[18];
    const float* bihr     = (const float*)d_in[19];
    const float* bhhr     = (const float*)d_in[20];
    const float* fc2_w    = (const float*)d_in[21];
    const float* fc2_b    = (const float*)d_in[22];
    float* out = (float*)d_out;

    float *px, *pkeys, *pctx, *ph;
    __half *phsh, *pw2h, *pwh, *pwl;
    cudaGetSymbolAddress((void**)&px,    g_x);
    cudaGetSymbolAddress((void**)&pkeys, g_keys);
    cudaGetSymbolAddress((void**)&pctx,  g_ctx);
    cudaGetSymbolAddress((void**)&ph,    g_h);
    cudaGetSymbolAddress((void**)&phsh,  g_hsh);
    cudaGetSymbolAddress((void**)&pw2h,  g_w2h);
    cudaGetSymbolAddress((void**)&pwh,   g_wh);
    cudaGetSymbolAddress((void**)&pwl,   g_wl);

    cudaFuncSetAttribute(fc2_mma_fp16, cudaFuncAttributeMaxDynamicSharedMemorySize, F2_SMEM);
    cudaFuncSetAttribute(keys_mma,     cudaFuncAttributeMaxDynamicSharedMemorySize, K_SMEMB);
    cudaFuncSetAttribute(gru_fp16<6>,  cudaFuncAttributeMaxDynamicSharedMemorySize, GR_SMEM);
    cudaFuncSetAttribute(gru_fp16<4>,  cudaFuncAttributeMaxDynamicSharedMemorySize, GR_SMEM);

    init_kernel<<<1024, 256>>>();
    cvt_w2_kernel<<<VOCAB*HID/8/256, 256>>>(fc2_w);

    // GRU weights -> packed fp16 hi/lo
    wsplit_gru<<<(1536*1536/8 + 255)/256, 256>>>(pwh, pwl, wih0, whh0, 1024, 1536);
    for (int l = 1; l < 4; l++) {
        size_t off = (size_t)1536*1536 + (size_t)(l-1)*1536*1024;
        wsplit_gru<<<(1536*1024/8 + 255)/256, 256>>>(
            pwh + off, pwl + off,
            wihr + (size_t)(l-1)*1536*512, whhr + (size_t)(l-1)*1536*512, 512, 1024);
    }

    gemm_big<1><<<dim3(4, 15), 256>>>(emb, fc1_w, fc1_b, px, 512, 512, caps);
    keys_mma<<<dim3(2, 49), 256, K_SMEMB>>>(features, wk, bk, pkeys);

    for (int t = 0; t < NSTEP; t++) {
        const float* hold = ph + (t & 1) * (4 * BH);
        float*       hnew = ph + ((t & 1) ^ 1) * (4 * BH);

        att_fused<<<128, 256>>>(hold + 3 * BH, wq, bq, pkeys, features,
                                v_w, v_b, fc0_w, fc0_b, pctx);

        // layer 0: [x | ctx | h], K=1536, NK=6
        gru_fp16<6><<<dim3(24, 6), 256, GR_SMEM>>>(
            px + t * HID, NSTEP * HID, pctx, hold,
            pwh, pwl, 1536, bih0, bhh0, hold, hnew, nullptr);

        for (int l = 1; l < 4; l++) {
            size_t off = (size_t)1536*1536 + (size_t)(l-1)*1536*1024;
            gru_fp16<4><<<dim3(24, 4), 256, GR_SMEM>>>(
                hnew + (l-1) * BH, 512, hold + l * BH, nullptr,
                pwh + off, pwl + off, 1024,
                bihr + (l-1) * 1536, bhhr + (l-1) * 1536,
                hold + l * BH, hnew + l * BH,
                (l == 3) ? (phsh + t * BH) : nullptr);
        }
    }

    fc2_mma_fp16<<<dim3(VOCAB/256, NSTEP), 256, F2_SMEM>>>(phsh, pw2h, fc2_b, out);
}